// round 5
// baseline (speedup 1.0000x reference)
#include <cuda_runtime.h>
#include <math.h>

#define N_IMG 4
#define C_IN 512
#define SP 4096              // 64*64 per image
#define KTOT 4608            // 512*9
#define NANCH 36864          // 4096*9
#define NS 65536             // padded sort size per image
#define PRE 3000
#define POST 300
#define NWORDS 94            // ceil(3000/32)

// output layout (concatenated float32, reference return order)
#define OFF_LOC 0
#define OFF_SC  589824
#define OFF_ROI 884736
#define OFF_VAL 889536
#define OFF_ANC 890736

// -------- scratch (static device globals; no allocation) --------
__device__ float g_h[N_IMG * C_IN * SP];          // conv1 output, NCHW
__device__ float g_wt[KTOT * C_IN];               // W1 transposed, K reordered r*512+c
__device__ float g_fg[N_IMG * NANCH];             // softmax fg scores
__device__ float g_boxes[N_IMG * NANCH * 4];      // decoded+clipped boxes
__device__ unsigned long long g_keys[N_IMG * NS]; // sort keys
__device__ float g_selbox[N_IMG * PRE * 4];       // top-3000 boxes
__device__ int   g_selfin[N_IMG * PRE];           // finite-score flag
__device__ unsigned g_mask[N_IMG * PRE * NWORDS]; // iou>0.7 bitmask rows

__device__ __forceinline__ float read_scalar(const int* p) {
    int iv = *p;
    if (iv > 0 && iv < (1 << 24)) return (float)iv;
    return *reinterpret_cast<const float*>(p);
}

union F2U { unsigned long long u; float2 f; };

#define FMA2(d, a, b) asm("fma.rn.f32x2 %0, %1, %2, %0;" : "+l"(d) : "l"(a), "l"(b))

// ===================== pre-conv kernels (conv must be 4th launch for ncu) =====================
__global__ void anchors_kernel(float* __restrict__ anch_out)
{
    int li = blockIdx.x * blockDim.x + threadIdx.x;
    if (li >= NANCH) return;
    int pix = li / 9;
    int a = li - pix * 9;
    int y = pix >> 6, x = pix & 63;
    int ri = a / 3, si = a - ri * 3;
    float ratio = (ri == 0) ? 0.5f : ((ri == 1) ? 1.0f : 2.0f);
    float scl = (si == 0) ? 8.f : ((si == 1) ? 16.f : 32.f);
    float hs = (16.f * scl) * sqrtf(ratio);
    float ws = (16.f * scl) * sqrtf(1.0f / ratio);
    float sy = (float)(y * 16), sx = (float)(x * 16);
    float* ap = anch_out + (size_t)li * 4;
    ap[0] = sy + (8.f - hs * 0.5f);
    ap[1] = sx + (8.f - ws * 0.5f);
    ap[2] = sy + (8.f + hs * 0.5f);
    ap[3] = sx + (8.f + ws * 0.5f);
}

__global__ void pad_keys_kernel()
{
    int t = blockIdx.x * blockDim.x + threadIdx.x;
    int per = NS - NANCH;               // 28672
    if (t >= N_IMG * per) return;
    int img = t / per, li = NANCH + (t - img * per);
    g_keys[(size_t)img * NS + li] = 0xFFFFFFFFFFFFFFFFull;
}

// W1[m][c*9+r]  ->  g_wt[(r*512+c)*512 + m]
__global__ void wtrans_kernel(const float* __restrict__ W1)
{
    int t = blockIdx.x * blockDim.x + threadIdx.x;
    if (t >= KTOT * C_IN) return;
    int k = t >> 9, m = t & 511;
    int rr = k >> 9, c = k & 511;
    g_wt[t] = W1[(size_t)m * KTOT + c * 9 + rr];
}

// ===================== conv 3x3, 512->512, pad 1, + bias + relu =====================
// implicit GEMM, K reordered: k = r*512 + c  (r = spatial tap, outer; c = channel, inner)
// tile 128x128, 256 threads, thread tile 8m x 8n as 32 f32x2 accumulators
// A smem: duplicated pairs (a,a); B smem: XOR-swizzled float4 chunks (f -> f ^ (f>>3))
__global__ __launch_bounds__(256, 2) void conv3x3_kernel(
    const float* __restrict__ x, const float* __restrict__ bias)
{
    __shared__ float Asd[2][8][256];   // [kk][2m]=[kk][2m+1]=W[m]
    __shared__ float Bs[2][8][128];    // swizzled chunk layout

    const int tid = threadIdx.x;
    const int n0 = blockIdx.x * 128;
    const int m0 = blockIdx.y * 128;

    // ---- B (im2col) per-thread slots: 4 values per K-step ----
    int by[4], bx[4];
    const float* xb[4];
    float* bst[4];                    // swizzled store target in Bs[0]
    int off[4]; bool pred[4];
#pragma unroll
    for (int i = 0; i < 4; i++) {
        int idx = tid + i * 256;
        int bks = idx >> 7;
        int bn = idx & 127;
        int col = n0 + bn;
        int img = col >> 12;
        by[i] = (col >> 6) & 63;
        bx[i] = col & 63;
        xb[i] = x + (size_t)img * (C_IN * SP) + (size_t)bks * SP;
        int f = bn >> 2, c = bn & 3;
        int scol = ((f ^ (f >> 3)) << 2) | c;       // XOR swizzle
        bst[i] = &Bs[0][bks][scol];
    }

#define SETOFF(RR) do { \
    int ky = (RR) / 3, kx = (RR) - 3 * (ky); \
    _Pragma("unroll") \
    for (int i = 0; i < 4; i++) { \
        int yy = by[i] + ky - 1, xx = bx[i] + kx - 1; \
        pred[i] = ((unsigned)yy < 64u) && ((unsigned)xx < 64u); \
        off[i] = (yy << 6) + xx; \
    } } while (0)

    // ---- A fill ----
    const int kq = tid >> 5;            // 0..7
    const int mm = (tid & 31) * 4;      // 0..124
    const float* Aptr = g_wt + (size_t)kq * C_IN + m0 + mm;

    unsigned long long acc[8][4];
#pragma unroll
    for (int mi = 0; mi < 8; mi++)
#pragma unroll
        for (int ni = 0; ni < 4; ni++) acc[mi][ni] = 0ull;

    const int tm = tid >> 4;            // 0..15
    const int tn = tid & 15;            // 0..15
    // reader swizzled chunk indices (longlong2 units == float4 chunks)
    const int f0 = tn * 2;
    const int sw0 = f0 ^ (f0 >> 3);
    const int sw1 = (f0 + 1) ^ ((f0 + 1) >> 3);

    float4 aw;
    float bv[4];

#define LOAD_B(C0E) do { \
    _Pragma("unroll") \
    for (int i = 0; i < 4; i++) \
        bv[i] = pred[i] ? __ldg(xb[i] + (C0E) + off[i]) : 0.f; \
    } while (0)

#define STS_AB(BUF) do { \
    float* ad = &Asd[BUF][kq][2 * mm]; \
    _Pragma("unroll") \
    for (int j = 0; j < 4; j++) { \
        float v = (&aw.x)[j]; \
        *reinterpret_cast<float2*>(ad + 2 * j) = make_float2(v, v); \
    } \
    _Pragma("unroll") \
    for (int i = 0; i < 4; i++) bst[i][(BUF) * (8 * 128)] = bv[i]; \
    } while (0)

    SETOFF(0);
    aw = *reinterpret_cast<const float4*>(Aptr);
    LOAD_B(0);
    STS_AB(0);
    __syncthreads();

    int buf = 0;
    for (int s = 0; s < 576; s++) {
        const bool more = s < 575;
        if (more) {
            Aptr += 8 * C_IN;
            aw = *reinterpret_cast<const float4*>(Aptr);
            int sn = s + 1;
            if ((sn & 63) == 0) SETOFF(sn >> 6);
            LOAD_B((sn & 63) << 15);
        }

#pragma unroll
        for (int kk = 0; kk < 8; kk++) {
            const longlong2* Bp = reinterpret_cast<const longlong2*>(&Bs[buf][kk][0]);
            longlong2 L0 = Bp[sw0];
            longlong2 L1 = Bp[sw1];
            unsigned long long b0 = (unsigned long long)L0.x, b1 = (unsigned long long)L0.y;
            unsigned long long b2 = (unsigned long long)L1.x, b3 = (unsigned long long)L1.y;
            const longlong2* Ap = reinterpret_cast<const longlong2*>(&Asd[buf][kk][tm * 16]);
            longlong2 A0 = Ap[0], A1 = Ap[1], A2 = Ap[2], A3 = Ap[3];
            unsigned long long a2[8] = {
                (unsigned long long)A0.x, (unsigned long long)A0.y,
                (unsigned long long)A1.x, (unsigned long long)A1.y,
                (unsigned long long)A2.x, (unsigned long long)A2.y,
                (unsigned long long)A3.x, (unsigned long long)A3.y };
#pragma unroll
            for (int mi = 0; mi < 8; mi++) {
                FMA2(acc[mi][0], a2[mi], b0);
                FMA2(acc[mi][1], a2[mi], b1);
                FMA2(acc[mi][2], a2[mi], b2);
                FMA2(acc[mi][3], a2[mi], b3);
            }
        }

        if (more) STS_AB(buf ^ 1);
        __syncthreads();
        buf ^= 1;
    }

    const int colbase = n0 + tn * 8;
    const int img = colbase >> 12;
    const int spbase = colbase & 4095;
#pragma unroll
    for (int mi = 0; mi < 8; mi++) {
        int m = m0 + tm * 8 + mi;
        float bvv = bias[m];
        float* hp = g_h + ((size_t)img * C_IN + m) * SP + spbase;
#pragma unroll
        for (int ni = 0; ni < 4; ni++) {
            F2U u; u.u = acc[mi][ni];
            float2 v;
            v.x = fmaxf(u.f.x + bvv, 0.f);
            v.y = fmaxf(u.f.y + bvv, 0.f);
            *reinterpret_cast<float2*>(hp + ni * 2) = v;
        }
    }
}

// ===================== heads: 1x1 convs (18 score, 36 loc), transpose, softmax =====================
__global__ __launch_bounds__(128) void heads_kernel(
    const float* __restrict__ Ws, const float* __restrict__ bs,
    const float* __restrict__ Wl, const float* __restrict__ bl,
    float* __restrict__ out)
{
    __shared__ float Wt[54][64];
    const int tid = threadIdx.x;
    const int col = blockIdx.x * 128 + tid;
    const int img = col >> 12;
    const int sp = col & 4095;

    float acc[54];
#pragma unroll
    for (int o = 0; o < 54; o++) acc[o] = 0.f;

    for (int c0 = 0; c0 < C_IN; c0 += 64) {
        for (int i = tid; i < 54 * 64; i += 128) {
            int o = i >> 6, cc = i & 63;
            Wt[o][cc] = (o < 18) ? Ws[o * C_IN + c0 + cc] : Wl[(o - 18) * C_IN + c0 + cc];
        }
        __syncthreads();
        const float* hp = g_h + (size_t)img * C_IN * SP + (size_t)c0 * SP + sp;
#pragma unroll 4
        for (int cc = 0; cc < 64; cc++) {
            float xv = hp[(size_t)cc * SP];
#pragma unroll
            for (int o = 0; o < 54; o++) acc[o] += xv * Wt[o][cc];
        }
        __syncthreads();
    }

    const size_t base9 = (size_t)img * NANCH + (size_t)sp * 9;
#pragma unroll
    for (int o = 0; o < 18; o++) {
        float v = acc[o] + bs[o];
        out[OFF_SC + (base9 + (o >> 1)) * 2 + (o & 1)] = v;
    }
#pragma unroll
    for (int o = 0; o < 36; o++) {
        float v = acc[18 + o] + bl[o];
        out[OFF_LOC + (base9 + (o >> 2)) * 4 + (o & 3)] = v;
    }
#pragma unroll
    for (int a = 0; a < 9; a++) {
        float s0 = acc[2 * a] + bs[2 * a];
        float s1 = acc[2 * a + 1] + bs[2 * a + 1];
        float m = fmaxf(s0, s1);
        float e0 = expf(s0 - m), e1 = expf(s1 - m);
        g_fg[base9 + a] = e1 / (e0 + e1);
    }
}

// ===================== loc2bbox + clip + min-size + sort keys =====================
__global__ void boxes_kernel(const float* __restrict__ locs,
                             const int* __restrict__ imh_p, const int* __restrict__ imw_p)
{
    int t = blockIdx.x * blockDim.x + threadIdx.x;
    if (t >= N_IMG * NANCH) return;
    int img = t / NANCH;
    int li = t - img * NANCH;

    int pix = li / 9;
    int a = li - pix * 9;
    int y = pix >> 6, x = pix & 63;
    int ri = a / 3, si = a - ri * 3;
    float ratio = (ri == 0) ? 0.5f : ((ri == 1) ? 1.0f : 2.0f);
    float scl = (si == 0) ? 8.f : ((si == 1) ? 16.f : 32.f);
    float hs = (16.f * scl) * sqrtf(ratio);
    float ws = (16.f * scl) * sqrtf(1.0f / ratio);
    float sy = (float)(y * 16), sx = (float)(x * 16);
    float ay1 = sy + (8.f - hs * 0.5f);
    float ax1 = sx + (8.f - ws * 0.5f);
    float ay2 = sy + (8.f + hs * 0.5f);
    float ax2 = sx + (8.f + ws * 0.5f);

    const float* lp = locs + ((size_t)img * NANCH + li) * 4;
    float dy = lp[0], dx = lp[1], dh = lp[2], dw = lp[3];
    float ah = ay2 - ay1, aw = ax2 - ax1;
    float acy = ay1 + 0.5f * ah, acx = ax1 + 0.5f * aw;
    float cy = dy * ah + acy, cx = dx * aw + acx;
    float hb = expf(dh) * ah, wb = expf(dw) * aw;

    float imh = read_scalar(imh_p);
    float imw = read_scalar(imw_p);
    float y1 = fminf(fmaxf(cy - 0.5f * hb, 0.f), imh);
    float x1 = fminf(fmaxf(cx - 0.5f * wb, 0.f), imw);
    float y2 = fminf(fmaxf(cy + 0.5f * hb, 0.f), imh);
    float x2 = fminf(fmaxf(cx + 0.5f * wb, 0.f), imw);

    float* bp = g_boxes + ((size_t)img * NANCH + li) * 4;
    bp[0] = y1; bp[1] = x1; bp[2] = y2; bp[3] = x2;

    bool valid = ((y2 - y1) >= 16.f) && ((x2 - x1) >= 16.f);
    float s = valid ? g_fg[(size_t)img * NANCH + li] : -INFINITY;
    unsigned u = __float_as_uint(s);
    unsigned desc = (u & 0x80000000u) ? u : (~u & 0x7FFFFFFFu);   // ascending key = descending score
    g_keys[(size_t)img * NS + li] = ((unsigned long long)desc << 32) | (unsigned)li;
}

// ===================== bitonic sort (per-image 65536 keys, ascending) =====================
__global__ __launch_bounds__(512) void sort_local8k()
{
    extern __shared__ unsigned long long s[];
    const int base = blockIdx.x * 8192;
    for (int i = threadIdx.x; i < 8192; i += 512) s[i] = g_keys[base + i];
    __syncthreads();
    for (int k = 2; k <= 8192; k <<= 1) {
        for (int j = k >> 1; j > 0; j >>= 1) {
            for (int t = threadIdx.x; t < 4096; t += 512) {
                int i = ((t & ~(j - 1)) << 1) | (t & (j - 1));
                int l = i | j;
                bool up = (((base + i) & k) == 0);
                unsigned long long va = s[i], vb = s[l];
                if ((va > vb) == up) { s[i] = vb; s[l] = va; }
            }
            __syncthreads();
        }
    }
    for (int i = threadIdx.x; i < 8192; i += 512) g_keys[base + i] = s[i];
}

__global__ void sort_global(int k, int j)
{
    int t = blockIdx.x * blockDim.x + threadIdx.x;  // 4*32768
    int img = t >> 15, tt = t & 32767;
    int i = ((tt & ~(j - 1)) << 1) | (tt & (j - 1));
    int l = i | j;
    unsigned long long* p = g_keys + (size_t)img * NS;
    bool up = ((i & k) == 0);
    unsigned long long va = p[i], vb = p[l];
    if ((va > vb) == up) { p[i] = vb; p[l] = va; }
}

__global__ __launch_bounds__(512) void merge_local8k(int k)
{
    extern __shared__ unsigned long long s[];
    const int base = blockIdx.x * 8192;
    for (int i = threadIdx.x; i < 8192; i += 512) s[i] = g_keys[base + i];
    __syncthreads();
    bool up = (((base & (NS - 1)) & k) == 0);
    for (int j = 4096; j > 0; j >>= 1) {
        for (int t = threadIdx.x; t < 4096; t += 512) {
            int i = ((t & ~(j - 1)) << 1) | (t & (j - 1));
            int l = i | j;
            unsigned long long va = s[i], vb = s[l];
            if ((va > vb) == up) { s[i] = vb; s[l] = va; }
        }
        __syncthreads();
    }
    for (int i = threadIdx.x; i < 8192; i += 512) g_keys[base + i] = s[i];
}

// ===================== gather top-3000 =====================
__global__ void gather_kernel()
{
    int t = blockIdx.x * blockDim.x + threadIdx.x;
    if (t >= N_IMG * PRE) return;
    int img = t / PRE, r = t - img * PRE;
    unsigned long long key = g_keys[(size_t)img * NS + r];
    int li = (int)(key & 0xFFFFFFFFull);
    unsigned desc = (unsigned)(key >> 32);
    g_selfin[img * PRE + r] = (desc < 0xFF800000u) ? 1 : 0;  // finite score
    float4 b = *reinterpret_cast<const float4*>(&g_boxes[((size_t)img * NANCH + li) * 4]);
    *reinterpret_cast<float4*>(&g_selbox[((size_t)img * PRE + r) * 4]) = b;
}

// ===================== IoU > 0.7 bitmask =====================
__global__ void iou_kernel()
{
    int t = blockIdx.x * blockDim.x + threadIdx.x;
    if (t >= N_IMG * PRE * NWORDS) return;
    int img = t / (PRE * NWORDS);
    int rem = t - img * (PRE * NWORDS);
    int i = rem / NWORDS;
    int w = rem - i * NWORDS;
    const float* B = g_selbox + (size_t)img * PRE * 4;
    float4 bi = *reinterpret_cast<const float4*>(B + (size_t)i * 4);
    float ai = (bi.z - bi.x) * (bi.w - bi.y);
    unsigned bits = 0;
    int j0 = w * 32;
#pragma unroll 4
    for (int jj = 0; jj < 32; jj++) {
        int j = j0 + jj;
        if (j >= PRE) break;
        float4 bj = *reinterpret_cast<const float4*>(B + (size_t)j * 4);
        float yy1 = fmaxf(bi.x, bj.x), xx1 = fmaxf(bi.y, bj.y);
        float yy2 = fminf(bi.z, bj.z), xx2 = fminf(bi.w, bj.w);
        float ih = fmaxf(yy2 - yy1, 0.f), iw = fmaxf(xx2 - xx1, 0.f);
        float inter = ih * iw;
        float aj = (bj.z - bj.x) * (bj.w - bj.y);
        float uni = ai + aj - inter;
        float iou = (uni > 0.f) ? (inter / uni) : 0.f;
        if (iou > 0.7f) bits |= (1u << jj);
    }
    g_mask[((size_t)img * PRE + i) * NWORDS + w] = bits;
}

// ===================== sequential greedy NMS with 8-deep row prefetch =====================
__global__ void nms_kernel(float* __restrict__ out)
{
    const int img = blockIdx.x;
    const int lane = threadIdx.x;
    __shared__ int kept[POST];
    __shared__ int s_nk;
    unsigned r0 = 0, r1 = 0, r2 = 0;   // lane owns removed-words [3*lane .. 3*lane+2]
    int nk = 0;
    const unsigned* M = g_mask + (size_t)img * PRE * NWORDS;
    const int* fin = g_selfin + img * PRE;
    const int b0 = lane * 3;
    const bool v0 = (b0 < NWORDS), v1 = (b0 + 1 < NWORDS), v2 = (b0 + 2 < NWORDS);

    unsigned p0[8], p1[8], p2[8];      // prefetched rows i..i+7
#pragma unroll
    for (int s = 0; s < 8; s++) {
        const unsigned* row = M + (size_t)s * NWORDS + b0;
        p0[s] = v0 ? __ldg(row) : 0u;
        p1[s] = v1 ? __ldg(row + 1) : 0u;
        p2[s] = v2 ? __ldg(row + 2) : 0u;
    }

    for (int ib = 0; ib < PRE; ib += 8) {
#pragma unroll
        for (int s = 0; s < 8; s++) {
            int i = ib + s;
            int wi = i >> 5;
            int owner = wi / 3, sub = wi - owner * 3;
            unsigned myw = (sub == 0) ? r0 : ((sub == 1) ? r1 : r2);
            unsigned word = __shfl_sync(0xffffffffu, myw, owner);
            if (!((word >> (i & 31)) & 1u)) {
                if (lane == 0 && fin[i] && nk < POST) { kept[nk] = i; nk++; }
                r0 |= p0[s]; r1 |= p1[s]; r2 |= p2[s];
            }
            int ip = i + 8;
            if (ip < PRE) {
                const unsigned* row = M + (size_t)ip * NWORDS + b0;
                p0[s] = v0 ? __ldg(row) : 0u;
                p1[s] = v1 ? __ldg(row + 1) : 0u;
                p2[s] = v2 ? __ldg(row + 2) : 0u;
            }
        }
        int cnt = __shfl_sync(0xffffffffu, nk, 0);
        if (cnt >= POST) break;
    }
    if (lane == 0) s_nk = nk;
    __syncwarp();
    int NK = s_nk;

    for (int r = lane; r < POST; r += 32) {
        float4 b = make_float4(0.f, 0.f, 0.f, 0.f);
        float v = 0.f;
        if (r < NK) {
            b = *reinterpret_cast<const float4*>(&g_selbox[((size_t)img * PRE + kept[r]) * 4]);
            v = 1.f;
        }
        float* rp = out + OFF_ROI + ((size_t)img * POST + r) * 4;
        rp[0] = b.x; rp[1] = b.y; rp[2] = b.z; rp[3] = b.w;
        out[OFF_VAL + img * POST + r] = v;
    }
}

// ===================== launch =====================
extern "C" void kernel_launch(void* const* d_in, const int* in_sizes, int n_in,
                              void* d_out, int out_size)
{
    const float* x  = (const float*)d_in[0];
    const float* W1 = (const float*)d_in[1];
    const float* b1 = (const float*)d_in[2];
    const float* Ws = (const float*)d_in[3];
    const float* bs = (const float*)d_in[4];
    const float* Wl = (const float*)d_in[5];
    const float* bl = (const float*)d_in[6];
    const int* imh  = (const int*)d_in[7];
    const int* imw  = (const int*)d_in[8];
    float* out = (float*)d_out;

    cudaFuncSetAttribute(sort_local8k, cudaFuncAttributeMaxDynamicSharedMemorySize, 65536);
    cudaFuncSetAttribute(merge_local8k, cudaFuncAttributeMaxDynamicSharedMemorySize, 65536);

    // conv is the 4th launch (the one ncu profiles)
    anchors_kernel<<<(NANCH + 255) / 256, 256>>>(out + OFF_ANC);
    pad_keys_kernel<<<(N_IMG * (NS - NANCH) + 255) / 256, 256>>>();
    wtrans_kernel<<<(KTOT * C_IN + 255) / 256, 256>>>(W1);

    conv3x3_kernel<<<dim3(128, 4), 256>>>(x, b1);
    heads_kernel<<<128, 128>>>(Ws, bs, Wl, bl, out);
    boxes_kernel<<<(N_IMG * NANCH + 255) / 256, 256>>>(out + OFF_LOC, imh, imw);

    sort_local8k<<<32, 512, 65536>>>();
    for (int k = 16384; k <= 65536; k <<= 1) {
        for (int j = k >> 1; j >= 8192; j >>= 1)
            sort_global<<<512, 256>>>(k, j);
        merge_local8k<<<32, 512, 65536>>>(k);
    }

    gather_kernel<<<(N_IMG * PRE + 255) / 256, 256>>>();
    iou_kernel<<<(N_IMG * PRE * NWORDS + 255) / 256, 256>>>();
    nms_kernel<<<4, 32>>>(out);
}

// round 10
// speedup vs baseline: 1.8182x; 1.8182x over previous
#include <cuda_runtime.h>
#include <math.h>
#include <stdint.h>

#define N_IMG 4
#define C_IN 512
#define SP 4096              // 64*64 per image
#define KTOT 4608            // 512*9
#define NANCH 36864          // 4096*9
#define NS 65536             // padded sort size per image
#define PRE 3000
#define POST 300
#define NWORDS 94            // ceil(3000/32)

// output layout (concatenated float32, reference return order)
#define OFF_LOC 0
#define OFF_SC  589824
#define OFF_ROI 884736
#define OFF_VAL 889536
#define OFF_ANC 890736

// -------- scratch (static device globals; no allocation) --------
__device__ float g_h[N_IMG * C_IN * SP];          // conv1 output, NCHW
__device__ float g_wt[KTOT * C_IN];               // W1 transposed, K reordered r*512+c
__device__ float g_fg[N_IMG * NANCH];             // softmax fg scores
__device__ float g_boxes[N_IMG * NANCH * 4];      // decoded+clipped boxes
__device__ unsigned long long g_keys[N_IMG * NS]; // sort keys
__device__ float g_selbox[N_IMG * PRE * 4];       // top-3000 boxes
__device__ int   g_selfin[N_IMG * PRE];           // finite-score flag
__device__ unsigned g_mask[N_IMG * PRE * NWORDS]; // iou>0.7 bitmask rows

__device__ __forceinline__ float read_scalar(const int* p) {
    int iv = *p;
    if (iv > 0 && iv < (1 << 24)) return (float)iv;
    return *reinterpret_cast<const float*>(p);
}

__device__ __forceinline__ uint32_t f2tf(float f) {
    uint32_t r;
    asm("cvt.rna.tf32.f32 %0, %1;" : "=r"(r) : "f"(f));
    return r;
}

// chained MMA: c += a*b
#define MMA_TF32(c, a, b) \
    asm volatile("mma.sync.aligned.m16n8k8.row.col.f32.tf32.tf32.f32 " \
        "{%0,%1,%2,%3},{%4,%5,%6,%7},{%8,%9},{%0,%1,%2,%3};" \
        : "+f"((c)[0]), "+f"((c)[1]), "+f"((c)[2]), "+f"((c)[3]) \
        : "r"((a)[0]), "r"((a)[1]), "r"((a)[2]), "r"((a)[3]), \
          "r"((b)[0]), "r"((b)[1]))

// fresh MMA: c = a*b + 0   (d != c; kills accumulator bias chains)
#define MMA_TF32_Z(c, a, b) \
    asm volatile("mma.sync.aligned.m16n8k8.row.col.f32.tf32.tf32.f32 " \
        "{%0,%1,%2,%3},{%4,%5,%6,%7},{%8,%9},{%10,%11,%12,%13};" \
        : "=f"((c)[0]), "=f"((c)[1]), "=f"((c)[2]), "=f"((c)[3]) \
        : "r"((a)[0]), "r"((a)[1]), "r"((a)[2]), "r"((a)[3]), \
          "r"((b)[0]), "r"((b)[1]), \
          "f"(0.f), "f"(0.f), "f"(0.f), "f"(0.f))

// ===================== pre-conv kernels (conv must be 4th launch for ncu) =====================
__global__ void anchors_kernel(float* __restrict__ anch_out)
{
    int li = blockIdx.x * blockDim.x + threadIdx.x;
    if (li >= NANCH) return;
    int pix = li / 9;
    int a = li - pix * 9;
    int y = pix >> 6, x = pix & 63;
    int ri = a / 3, si = a - ri * 3;
    float ratio = (ri == 0) ? 0.5f : ((ri == 1) ? 1.0f : 2.0f);
    float scl = (si == 0) ? 8.f : ((si == 1) ? 16.f : 32.f);
    float hs = (16.f * scl) * sqrtf(ratio);
    float ws = (16.f * scl) * sqrtf(1.0f / ratio);
    float sy = (float)(y * 16), sx = (float)(x * 16);
    float* ap = anch_out + (size_t)li * 4;
    ap[0] = sy + (8.f - hs * 0.5f);
    ap[1] = sx + (8.f - ws * 0.5f);
    ap[2] = sy + (8.f + hs * 0.5f);
    ap[3] = sx + (8.f + ws * 0.5f);
}

__global__ void pad_keys_kernel()
{
    int t = blockIdx.x * blockDim.x + threadIdx.x;
    int per = NS - NANCH;
    if (t >= N_IMG * per) return;
    int img = t / per, li = NANCH + (t - img * per);
    g_keys[(size_t)img * NS + li] = 0xFFFFFFFFFFFFFFFFull;
}

// W1[m][c*9+r]  ->  g_wt[(r*512+c)*512 + m]
__global__ void wtrans_kernel(const float* __restrict__ W1)
{
    int t = blockIdx.x * blockDim.x + threadIdx.x;
    if (t >= KTOT * C_IN) return;
    int k = t >> 9, m = t & 511;
    int rr = k >> 9, c = k & 511;
    g_wt[t] = W1[(size_t)m * KTOT + c * 9 + rr];
}

// ===================== conv 3x3 via mma.sync tf32 (3-pass hi/lo, segmented accum) =====================
// D[m][n] = sum_k W[m][k]*im2col[n][k], K reordered k = r*512 + c (tap-outer).
// CTA tile 128x128, 8 warps of 64x32; K chunk 16, double-buffered smem.
// Per 8-k halfchunk per 16x8 tile: 3 MMAs on a zero-seeded c-fragment, then
// RN FADD into persistent fp32 accumulators (bounds tensor-core accum error).
#define TPAD 136
#define TILE_F (16 * TPAD)                 // 2176 floats per tile
#define BUF_F (4 * TILE_F)                 // Ahi, Alo, Bhi, Blo
#define CONV_SMEM_B (2 * BUF_F * 4)        // 69632 bytes
#define NCH 288

__global__ __launch_bounds__(256) void conv3x3_kernel(
    const float* __restrict__ x, const float* __restrict__ bias)
{
    extern __shared__ float sm[];
    const int tid = threadIdx.x;
    const int n0 = blockIdx.x * 128;
    const int m0 = blockIdx.y * 128;
    const int wid = tid >> 5, lane = tid & 31;
    const int g = lane >> 2, tk = lane & 3;
    const int wm = wid >> 2, wn = wid & 3;

    // fill coordinates
    const int fk = tid >> 4;              // k row 0..15
    const int fp = (tid & 15) * 8;        // col base 0..120
    const int img = n0 >> 12;
    const int nb_ = n0 + fp;
    const int ybase = (nb_ >> 6) & 63;
    const int xbase = nb_ & 63;
    const float* xim = x + (size_t)img * (C_IN * SP);

    float sum[4][4][4];
#pragma unroll
    for (int a = 0; a < 4; a++)
#pragma unroll
        for (int b = 0; b < 4; b++)
#pragma unroll
            for (int c = 0; c < 4; c++) sum[a][b][c] = 0.f;

    float av[8], bv[8];

#define LOADG(CH) do { \
    const int k0 = (CH) << 4; \
    const int rr = (CH) >> 5; \
    const int cb = k0 & 511; \
    const int dy = rr / 3 - 1, dx = rr - 3 * (rr / 3) - 1; \
    const float* wp = g_wt + ((size_t)(k0 + fk) << 9) + m0 + fp; \
    float4 w0 = *reinterpret_cast<const float4*>(wp); \
    float4 w1 = *reinterpret_cast<const float4*>(wp + 4); \
    av[0]=w0.x; av[1]=w0.y; av[2]=w0.z; av[3]=w0.w; \
    av[4]=w1.x; av[5]=w1.y; av[6]=w1.z; av[7]=w1.w; \
    const int yy = ybase + dy; \
    const bool rok = (unsigned)yy < 64u; \
    const float* bp = xim + ((size_t)(cb + fk) << 12) + (yy << 6) + xbase + dx; \
    _Pragma("unroll") \
    for (int i = 0; i < 8; i++) { \
        int xx = xbase + dx + i; \
        bv[i] = (rok && (unsigned)xx < 64u) ? bp[i] : 0.f; \
    } } while (0)

#define CVSTORE(BUF) do { \
    float* SA = sm + (BUF) * BUF_F + fk * TPAD + fp; \
    float* SAl = SA + TILE_F; \
    float* SB = SA + 2 * TILE_F; \
    float* SBl = SA + 3 * TILE_F; \
    uint32_t h[8]; float l[8]; \
    _Pragma("unroll") \
    for (int i = 0; i < 8; i++) { h[i] = f2tf(av[i]); l[i] = av[i] - __uint_as_float(h[i]); } \
    *reinterpret_cast<uint4*>(SA) = make_uint4(h[0], h[1], h[2], h[3]); \
    *reinterpret_cast<uint4*>(SA + 4) = make_uint4(h[4], h[5], h[6], h[7]); \
    { uint32_t lt[8]; \
      _Pragma("unroll") for (int i = 0; i < 8; i++) lt[i] = f2tf(l[i]); \
      *reinterpret_cast<uint4*>(SAl) = make_uint4(lt[0], lt[1], lt[2], lt[3]); \
      *reinterpret_cast<uint4*>(SAl + 4) = make_uint4(lt[4], lt[5], lt[6], lt[7]); } \
    _Pragma("unroll") \
    for (int i = 0; i < 8; i++) { h[i] = f2tf(bv[i]); l[i] = bv[i] - __uint_as_float(h[i]); } \
    *reinterpret_cast<uint4*>(SB) = make_uint4(h[0], h[1], h[2], h[3]); \
    *reinterpret_cast<uint4*>(SB + 4) = make_uint4(h[4], h[5], h[6], h[7]); \
    { uint32_t lt[8]; \
      _Pragma("unroll") for (int i = 0; i < 8; i++) lt[i] = f2tf(l[i]); \
      *reinterpret_cast<uint4*>(SBl) = make_uint4(lt[0], lt[1], lt[2], lt[3]); \
      *reinterpret_cast<uint4*>(SBl + 4) = make_uint4(lt[4], lt[5], lt[6], lt[7]); } \
    } while (0)

    LOADG(0);
    CVSTORE(0);
    __syncthreads();

    int buf = 0;
    for (int ch = 0; ch < NCH; ch++) {
        const bool more = ch + 1 < NCH;
        if (more) LOADG(ch + 1);

        {
            const uint32_t* SA = reinterpret_cast<const uint32_t*>(sm + buf * BUF_F);
            const uint32_t* SAl = SA + TILE_F;
            const uint32_t* SB = SA + 2 * TILE_F;
            const uint32_t* SBl = SA + 3 * TILE_F;
            const int r0 = tk * TPAD;
            const int r4 = r0 + 4 * TPAD;
#pragma unroll
            for (int ks = 0; ks < 2; ks++) {
                const int ro = ks * 8 * TPAD;
                uint32_t bh[4][2], bl[4][2];
#pragma unroll
                for (int nf = 0; nf < 4; nf++) {
                    const int nb = wn * 32 + nf * 8 + g;
                    bh[nf][0] = SB[ro + r0 + nb];
                    bh[nf][1] = SB[ro + r4 + nb];
                    bl[nf][0] = SBl[ro + r0 + nb];
                    bl[nf][1] = SBl[ro + r4 + nb];
                }
#pragma unroll
                for (int mf = 0; mf < 4; mf++) {
                    const int mb = wm * 64 + mf * 16 + g;
                    uint32_t ah[4], al[4];
                    ah[0] = SA[ro + r0 + mb];     ah[1] = SA[ro + r0 + mb + 8];
                    ah[2] = SA[ro + r4 + mb];     ah[3] = SA[ro + r4 + mb + 8];
                    al[0] = SAl[ro + r0 + mb];    al[1] = SAl[ro + r0 + mb + 8];
                    al[2] = SAl[ro + r4 + mb];    al[3] = SAl[ro + r4 + mb + 8];
#pragma unroll
                    for (int nf = 0; nf < 4; nf++) {
                        float t[4];
                        MMA_TF32_Z(t, ah, bh[nf]);    // partial = Ahi*Bhi
                        MMA_TF32(t, ah, bl[nf]);      // + Ahi*Blo
                        MMA_TF32(t, al, bh[nf]);      // + Alo*Bhi
                        sum[mf][nf][0] += t[0];
                        sum[mf][nf][1] += t[1];
                        sum[mf][nf][2] += t[2];
                        sum[mf][nf][3] += t[3];
                    }
                }
            }
        }

        if (more) CVSTORE(buf ^ 1);
        __syncthreads();
        buf ^= 1;
    }

    // epilogue: bias + relu
    const int spb = n0 & 4095;
#pragma unroll
    for (int mf = 0; mf < 4; mf++) {
        const int m = m0 + wm * 64 + mf * 16 + g;
        const float bv0 = bias[m];
        const float bv1 = bias[m + 8];
        float* h0 = g_h + ((size_t)img * C_IN + m) * SP + spb;
        float* h1 = h0 + 8 * SP;
#pragma unroll
        for (int nf = 0; nf < 4; nf++) {
            const int nn = wn * 32 + nf * 8 + 2 * tk;
            float2 v0, v1;
            v0.x = fmaxf(sum[mf][nf][0] + bv0, 0.f);
            v0.y = fmaxf(sum[mf][nf][1] + bv0, 0.f);
            v1.x = fmaxf(sum[mf][nf][2] + bv1, 0.f);
            v1.y = fmaxf(sum[mf][nf][3] + bv1, 0.f);
            *reinterpret_cast<float2*>(h0 + nn) = v0;
            *reinterpret_cast<float2*>(h1 + nn) = v1;
        }
    }
}

// ===================== heads: 1x1 convs (18 score, 36 loc), transpose, softmax =====================
__global__ __launch_bounds__(128) void heads_kernel(
    const float* __restrict__ Ws, const float* __restrict__ bs,
    const float* __restrict__ Wl, const float* __restrict__ bl,
    float* __restrict__ out)
{
    __shared__ float Wt[54][64];
    const int tid = threadIdx.x;
    const int col = blockIdx.x * 128 + tid;
    const int img = col >> 12;
    const int sp = col & 4095;

    float acc[54];
#pragma unroll
    for (int o = 0; o < 54; o++) acc[o] = 0.f;

    for (int c0 = 0; c0 < C_IN; c0 += 64) {
        for (int i = tid; i < 54 * 64; i += 128) {
            int o = i >> 6, cc = i & 63;
            Wt[o][cc] = (o < 18) ? Ws[o * C_IN + c0 + cc] : Wl[(o - 18) * C_IN + c0 + cc];
        }
        __syncthreads();
        const float* hp = g_h + (size_t)img * C_IN * SP + (size_t)c0 * SP + sp;
#pragma unroll 4
        for (int cc = 0; cc < 64; cc++) {
            float xv = hp[(size_t)cc * SP];
#pragma unroll
            for (int o = 0; o < 54; o++) acc[o] += xv * Wt[o][cc];
        }
        __syncthreads();
    }

    const size_t base9 = (size_t)img * NANCH + (size_t)sp * 9;
#pragma unroll
    for (int o = 0; o < 18; o++) {
        float v = acc[o] + bs[o];
        out[OFF_SC + (base9 + (o >> 1)) * 2 + (o & 1)] = v;
    }
#pragma unroll
    for (int o = 0; o < 36; o++) {
        float v = acc[18 + o] + bl[o];
        out[OFF_LOC + (base9 + (o >> 2)) * 4 + (o & 3)] = v;
    }
#pragma unroll
    for (int a = 0; a < 9; a++) {
        float s0 = acc[2 * a] + bs[2 * a];
        float s1 = acc[2 * a + 1] + bs[2 * a + 1];
        float m = fmaxf(s0, s1);
        float e0 = expf(s0 - m), e1 = expf(s1 - m);
        g_fg[base9 + a] = e1 / (e0 + e1);
    }
}

// ===================== loc2bbox + clip + min-size + sort keys =====================
__global__ void boxes_kernel(const float* __restrict__ locs,
                             const int* __restrict__ imh_p, const int* __restrict__ imw_p)
{
    int t = blockIdx.x * blockDim.x + threadIdx.x;
    if (t >= N_IMG * NANCH) return;
    int img = t / NANCH;
    int li = t - img * NANCH;

    int pix = li / 9;
    int a = li - pix * 9;
    int y = pix >> 6, x = pix & 63;
    int ri = a / 3, si = a - ri * 3;
    float ratio = (ri == 0) ? 0.5f : ((ri == 1) ? 1.0f : 2.0f);
    float scl = (si == 0) ? 8.f : ((si == 1) ? 16.f : 32.f);
    float hs = (16.f * scl) * sqrtf(ratio);
    float ws = (16.f * scl) * sqrtf(1.0f / ratio);
    float sy = (float)(y * 16), sx = (float)(x * 16);
    float ay1 = sy + (8.f - hs * 0.5f);
    float ax1 = sx + (8.f - ws * 0.5f);
    float ay2 = sy + (8.f + hs * 0.5f);
    float ax2 = sx + (8.f + ws * 0.5f);

    const float* lp = locs + ((size_t)img * NANCH + li) * 4;
    float dy = lp[0], dx = lp[1], dh = lp[2], dw = lp[3];
    float ah = ay2 - ay1, aw = ax2 - ax1;
    float acy = ay1 + 0.5f * ah, acx = ax1 + 0.5f * aw;
    float cy = dy * ah + acy, cx = dx * aw + acx;
    float hb = expf(dh) * ah, wb = expf(dw) * aw;

    float imh = read_scalar(imh_p);
    float imw = read_scalar(imw_p);
    float y1 = fminf(fmaxf(cy - 0.5f * hb, 0.f), imh);
    float x1 = fminf(fmaxf(cx - 0.5f * wb, 0.f), imw);
    float y2 = fminf(fmaxf(cy + 0.5f * hb, 0.f), imh);
    float x2 = fminf(fmaxf(cx + 0.5f * wb, 0.f), imw);

    float* bp = g_boxes + ((size_t)img * NANCH + li) * 4;
    bp[0] = y1; bp[1] = x1; bp[2] = y2; bp[3] = x2;

    bool valid = ((y2 - y1) >= 16.f) && ((x2 - x1) >= 16.f);
    float s = valid ? g_fg[(size_t)img * NANCH + li] : -INFINITY;
    unsigned u = __float_as_uint(s);
    unsigned desc = (u & 0x80000000u) ? u : (~u & 0x7FFFFFFFu);   // ascending key = descending score
    g_keys[(size_t)img * NS + li] = ((unsigned long long)desc << 32) | (unsigned)li;
}

// ===================== bitonic sort (per-image 65536 keys, ascending) =====================
__global__ __launch_bounds__(512) void sort_local8k()
{
    extern __shared__ unsigned long long s[];
    const int base = blockIdx.x * 8192;
    for (int i = threadIdx.x; i < 8192; i += 512) s[i] = g_keys[base + i];
    __syncthreads();
    for (int k = 2; k <= 8192; k <<= 1) {
        for (int j = k >> 1; j > 0; j >>= 1) {
            for (int t = threadIdx.x; t < 4096; t += 512) {
                int i = ((t & ~(j - 1)) << 1) | (t & (j - 1));
                int l = i | j;
                bool up = (((base + i) & k) == 0);
                unsigned long long va = s[i], vb = s[l];
                if ((va > vb) == up) { s[i] = vb; s[l] = va; }
            }
            __syncthreads();
        }
    }
    for (int i = threadIdx.x; i < 8192; i += 512) g_keys[base + i] = s[i];
}

__global__ void sort_global(int k, int j)
{
    int t = blockIdx.x * blockDim.x + threadIdx.x;  // 4*32768
    int img = t >> 15, tt = t & 32767;
    int i = ((tt & ~(j - 1)) << 1) | (tt & (j - 1));
    int l = i | j;
    unsigned long long* p = g_keys + (size_t)img * NS;
    bool up = ((i & k) == 0);
    unsigned long long va = p[i], vb = p[l];
    if ((va > vb) == up) { p[i] = vb; p[l] = va; }
}

__global__ __launch_bounds__(512) void merge_local8k(int k)
{
    extern __shared__ unsigned long long s[];
    const int base = blockIdx.x * 8192;
    for (int i = threadIdx.x; i < 8192; i += 512) s[i] = g_keys[base + i];
    __syncthreads();
    bool up = (((base & (NS - 1)) & k) == 0);
    for (int j = 4096; j > 0; j >>= 1) {
        for (int t = threadIdx.x; t < 4096; t += 512) {
            int i = ((t & ~(j - 1)) << 1) | (t & (j - 1));
            int l = i | j;
            unsigned long long va = s[i], vb = s[l];
            if ((va > vb) == up) { s[i] = vb; s[l] = va; }
        }
        __syncthreads();
    }
    for (int i = threadIdx.x; i < 8192; i += 512) g_keys[base + i] = s[i];
}

// ===================== gather top-3000 =====================
__global__ void gather_kernel()
{
    int t = blockIdx.x * blockDim.x + threadIdx.x;
    if (t >= N_IMG * PRE) return;
    int img = t / PRE, r = t - img * PRE;
    unsigned long long key = g_keys[(size_t)img * NS + r];
    int li = (int)(key & 0xFFFFFFFFull);
    unsigned desc = (unsigned)(key >> 32);
    g_selfin[img * PRE + r] = (desc < 0xFF800000u) ? 1 : 0;  // finite score
    float4 b = *reinterpret_cast<const float4*>(&g_boxes[((size_t)img * NANCH + li) * 4]);
    *reinterpret_cast<float4*>(&g_selbox[((size_t)img * PRE + r) * 4]) = b;
}

// ===================== IoU > 0.7 bitmask =====================
__global__ void iou_kernel()
{
    int t = blockIdx.x * blockDim.x + threadIdx.x;
    if (t >= N_IMG * PRE * NWORDS) return;
    int img = t / (PRE * NWORDS);
    int rem = t - img * (PRE * NWORDS);
    int i = rem / NWORDS;
    int w = rem - i * NWORDS;
    const float* B = g_selbox + (size_t)img * PRE * 4;
    float4 bi = *reinterpret_cast<const float4*>(B + (size_t)i * 4);
    float ai = (bi.z - bi.x) * (bi.w - bi.y);
    unsigned bits = 0;
    int j0 = w * 32;
#pragma unroll 4
    for (int jj = 0; jj < 32; jj++) {
        int j = j0 + jj;
        if (j >= PRE) break;
        float4 bj = *reinterpret_cast<const float4*>(B + (size_t)j * 4);
        float yy1 = fmaxf(bi.x, bj.x), xx1 = fmaxf(bi.y, bj.y);
        float yy2 = fminf(bi.z, bj.z), xx2 = fminf(bi.w, bj.w);
        float ih = fmaxf(yy2 - yy1, 0.f), iw = fmaxf(xx2 - xx1, 0.f);
        float inter = ih * iw;
        float aj = (bj.z - bj.x) * (bj.w - bj.y);
        float uni = ai + aj - inter;
        float iou = (uni > 0.f) ? (inter / uni) : 0.f;
        if (iou > 0.7f) bits |= (1u << jj);
    }
    g_mask[((size_t)img * PRE + i) * NWORDS + w] = bits;
}

// ===================== sequential greedy NMS with 8-deep row prefetch =====================
__global__ void nms_kernel(float* __restrict__ out)
{
    const int img = blockIdx.x;
    const int lane = threadIdx.x;
    __shared__ int kept[POST];
    __shared__ int s_nk;
    unsigned r0 = 0, r1 = 0, r2 = 0;   // lane owns removed-words [3*lane .. 3*lane+2]
    int nk = 0;
    const unsigned* M = g_mask + (size_t)img * PRE * NWORDS;
    const int* fin = g_selfin + img * PRE;
    const int b0 = lane * 3;
    const bool v0 = (b0 < NWORDS), v1 = (b0 + 1 < NWORDS), v2 = (b0 + 2 < NWORDS);

    unsigned p0[8], p1[8], p2[8];      // prefetched rows i..i+7
#pragma unroll
    for (int s = 0; s < 8; s++) {
        const unsigned* row = M + (size_t)s * NWORDS + b0;
        p0[s] = v0 ? __ldg(row) : 0u;
        p1[s] = v1 ? __ldg(row + 1) : 0u;
        p2[s] = v2 ? __ldg(row + 2) : 0u;
    }

    for (int ib = 0; ib < PRE; ib += 8) {
#pragma unroll
        for (int s = 0; s < 8; s++) {
            int i = ib + s;
            int wi = i >> 5;
            int owner = wi / 3, sub = wi - owner * 3;
            unsigned myw = (sub == 0) ? r0 : ((sub == 1) ? r1 : r2);
            unsigned word = __shfl_sync(0xffffffffu, myw, owner);
            if (!((word >> (i & 31)) & 1u)) {
                if (lane == 0 && fin[i] && nk < POST) { kept[nk] = i; nk++; }
                r0 |= p0[s]; r1 |= p1[s]; r2 |= p2[s];
            }
            int ip = i + 8;
            if (ip < PRE) {
                const unsigned* row = M + (size_t)ip * NWORDS + b0;
                p0[s] = v0 ? __ldg(row) : 0u;
                p1[s] = v1 ? __ldg(row + 1) : 0u;
                p2[s] = v2 ? __ldg(row + 2) : 0u;
            }
        }
        int cnt = __shfl_sync(0xffffffffu, nk, 0);
        if (cnt >= POST) break;
    }
    if (lane == 0) s_nk = nk;
    __syncwarp();
    int NK = s_nk;

    for (int r = lane; r < POST; r += 32) {
        float4 b = make_float4(0.f, 0.f, 0.f, 0.f);
        float v = 0.f;
        if (r < NK) {
            b = *reinterpret_cast<const float4*>(&g_selbox[((size_t)img * PRE + kept[r]) * 4]);
            v = 1.f;
        }
        float* rp = out + OFF_ROI + ((size_t)img * POST + r) * 4;
        rp[0] = b.x; rp[1] = b.y; rp[2] = b.z; rp[3] = b.w;
        out[OFF_VAL + img * POST + r] = v;
    }
}

// ===================== launch =====================
extern "C" void kernel_launch(void* const* d_in, const int* in_sizes, int n_in,
                              void* d_out, int out_size)
{
    const float* x  = (const float*)d_in[0];
    const float* W1 = (const float*)d_in[1];
    const float* b1 = (const float*)d_in[2];
    const float* Ws = (const float*)d_in[3];
    const float* bs = (const float*)d_in[4];
    const float* Wl = (const float*)d_in[5];
    const float* bl = (const float*)d_in[6];
    const int* imh  = (const int*)d_in[7];
    const int* imw  = (const int*)d_in[8];
    float* out = (float*)d_out;

    cudaFuncSetAttribute(sort_local8k, cudaFuncAttributeMaxDynamicSharedMemorySize, 65536);
    cudaFuncSetAttribute(merge_local8k, cudaFuncAttributeMaxDynamicSharedMemorySize, 65536);
    cudaFuncSetAttribute(conv3x3_kernel, cudaFuncAttributeMaxDynamicSharedMemorySize, CONV_SMEM_B);

    // conv is the 4th launch (the one ncu profiles)
    anchors_kernel<<<(NANCH + 255) / 256, 256>>>(out + OFF_ANC);
    pad_keys_kernel<<<(N_IMG * (NS - NANCH) + 255) / 256, 256>>>();
    wtrans_kernel<<<(KTOT * C_IN + 255) / 256, 256>>>(W1);

    conv3x3_kernel<<<dim3(128, 4), 256, CONV_SMEM_B>>>(x, b1);
    heads_kernel<<<128, 128>>>(Ws, bs, Wl, bl, out);
    boxes_kernel<<<(N_IMG * NANCH + 255) / 256, 256>>>(out + OFF_LOC, imh, imw);

    sort_local8k<<<32, 512, 65536>>>();
    for (int k = 16384; k <= 65536; k <<= 1) {
        for (int j = k >> 1; j >= 8192; j >>= 1)
            sort_global<<<512, 256>>>(k, j);
        merge_local8k<<<32, 512, 65536>>>(k);
    }

    gather_kernel<<<(N_IMG * PRE + 255) / 256, 256>>>();
    iou_kernel<<<(N_IMG * PRE * NWORDS + 255) / 256, 256>>>();
    nms_kernel<<<4, 32>>>(out);
}

// round 11
// speedup vs baseline: 1.9264x; 1.0595x over previous
#include <cuda_runtime.h>
#include <math.h>
#include <stdint.h>

#define N_IMG 4
#define C_IN 512
#define SP 4096              // 64*64 per image
#define KTOT 4608            // 512*9
#define NANCH 36864          // 4096*9
#define NS 65536             // padded sort size per image
#define PRE 3000
#define POST 300
#define NWORDS 94            // ceil(3000/32)

// output layout (concatenated float32, reference return order)
#define OFF_LOC 0
#define OFF_SC  589824
#define OFF_ROI 884736
#define OFF_VAL 889536
#define OFF_ANC 890736

// -------- scratch (static device globals; no allocation) --------
__device__ float g_h[N_IMG * C_IN * SP];          // conv1 output, NCHW
__device__ float g_wt[KTOT * C_IN];               // W1 transposed, K reordered r*512+c
__device__ float g_fg[N_IMG * NANCH];             // softmax fg scores
__device__ float g_boxes[N_IMG * NANCH * 4];      // decoded+clipped boxes
__device__ unsigned long long g_keys[N_IMG * NS]; // sort keys
__device__ float g_selbox[N_IMG * PRE * 4];       // top-3000 boxes
__device__ int   g_selfin[N_IMG * PRE];           // finite-score flag
__device__ unsigned g_mask[N_IMG * PRE * NWORDS]; // iou>0.7 bitmask rows

__device__ __forceinline__ float read_scalar(const int* p) {
    int iv = *p;
    if (iv > 0 && iv < (1 << 24)) return (float)iv;
    return *reinterpret_cast<const float*>(p);
}

__device__ __forceinline__ uint32_t f2tf(float f) {
    uint32_t r;
    asm("cvt.rna.tf32.f32 %0, %1;" : "=r"(r) : "f"(f));
    return r;
}

// chained MMA: c += a*b
#define MMA_TF32(c, a, b) \
    asm volatile("mma.sync.aligned.m16n8k8.row.col.f32.tf32.tf32.f32 " \
        "{%0,%1,%2,%3},{%4,%5,%6,%7},{%8,%9},{%0,%1,%2,%3};" \
        : "+f"((c)[0]), "+f"((c)[1]), "+f"((c)[2]), "+f"((c)[3]) \
        : "r"((a)[0]), "r"((a)[1]), "r"((a)[2]), "r"((a)[3]), \
          "r"((b)[0]), "r"((b)[1]))

// fresh MMA: c = a*b + 0   (d != c; kills accumulator bias chains)
#define MMA_TF32_Z(c, a, b) \
    asm volatile("mma.sync.aligned.m16n8k8.row.col.f32.tf32.tf32.f32 " \
        "{%0,%1,%2,%3},{%4,%5,%6,%7},{%8,%9},{%10,%11,%12,%13};" \
        : "=f"((c)[0]), "=f"((c)[1]), "=f"((c)[2]), "=f"((c)[3]) \
        : "r"((a)[0]), "r"((a)[1]), "r"((a)[2]), "r"((a)[3]), \
          "r"((b)[0]), "r"((b)[1]), \
          "f"(0.f), "f"(0.f), "f"(0.f), "f"(0.f))

// ===================== pre-conv kernels (conv must be 4th launch for ncu) =====================
__global__ void anchors_kernel(float* __restrict__ anch_out)
{
    int li = blockIdx.x * blockDim.x + threadIdx.x;
    if (li >= NANCH) return;
    int pix = li / 9;
    int a = li - pix * 9;
    int y = pix >> 6, x = pix & 63;
    int ri = a / 3, si = a - ri * 3;
    float ratio = (ri == 0) ? 0.5f : ((ri == 1) ? 1.0f : 2.0f);
    float scl = (si == 0) ? 8.f : ((si == 1) ? 16.f : 32.f);
    float hs = (16.f * scl) * sqrtf(ratio);
    float ws = (16.f * scl) * sqrtf(1.0f / ratio);
    float sy = (float)(y * 16), sx = (float)(x * 16);
    float* ap = anch_out + (size_t)li * 4;
    ap[0] = sy + (8.f - hs * 0.5f);
    ap[1] = sx + (8.f - ws * 0.5f);
    ap[2] = sy + (8.f + hs * 0.5f);
    ap[3] = sx + (8.f + ws * 0.5f);
}

__global__ void pad_keys_kernel()
{
    int t = blockIdx.x * blockDim.x + threadIdx.x;
    int per = NS - NANCH;
    if (t >= N_IMG * per) return;
    int img = t / per, li = NANCH + (t - img * per);
    g_keys[(size_t)img * NS + li] = 0xFFFFFFFFFFFFFFFFull;
}

// W1[m][c*9+r]  ->  g_wt[(r*512+c)*512 + m]
__global__ void wtrans_kernel(const float* __restrict__ W1)
{
    int t = blockIdx.x * blockDim.x + threadIdx.x;
    if (t >= KTOT * C_IN) return;
    int k = t >> 9, m = t & 511;
    int rr = k >> 9, c = k & 511;
    g_wt[t] = W1[(size_t)m * KTOT + c * 9 + rr];
}

// ===================== conv 3x3 via mma.sync tf32 (3-pass hi/lo, segmented accum) =====================
// D[m][n] = sum_k W[m][k]*im2col[n][k], K reordered k = r*512 + c (tap-outer).
// CTA tile 128x128, 8 warps of 64x32; K chunk 16, double-buffered smem.
// Per 8-k halfchunk per 16x8 tile: 3 MMAs on a zero-seeded c-fragment, then
// RN FADD into persistent fp32 accumulators (bounds tensor-core accum error).
// __launch_bounds__(256,2): cap 128 regs so 2 CTAs/SM fit (RF was the limiter).
#define TPAD 136
#define TILE_F (16 * TPAD)                 // 2176 floats per tile
#define BUF_F (4 * TILE_F)                 // Ahi, Alo, Bhi, Blo
#define CONV_SMEM_B (2 * BUF_F * 4)        // 69632 bytes
#define NCH 288

__global__ __launch_bounds__(256, 2) void conv3x3_kernel(
    const float* __restrict__ x, const float* __restrict__ bias)
{
    extern __shared__ float sm[];
    const int tid = threadIdx.x;
    const int n0 = blockIdx.x * 128;
    const int m0 = blockIdx.y * 128;
    const int wid = tid >> 5, lane = tid & 31;
    const int g = lane >> 2, tk = lane & 3;
    const int wm = wid >> 2, wn = wid & 3;

    // fill coordinates
    const int fk = tid >> 4;              // k row 0..15
    const int fp = (tid & 15) * 8;        // col base 0..120
    const int img = n0 >> 12;
    const int nb_ = n0 + fp;
    const int ybase = (nb_ >> 6) & 63;
    const int xbase = nb_ & 63;
    const float* xim = x + (size_t)img * (C_IN * SP);

    float sum[4][4][4];
#pragma unroll
    for (int a = 0; a < 4; a++)
#pragma unroll
        for (int b = 0; b < 4; b++)
#pragma unroll
            for (int c = 0; c < 4; c++) sum[a][b][c] = 0.f;

    float av[8], bv[8];

#define LOADG(CH) do { \
    const int k0 = (CH) << 4; \
    const int rr = (CH) >> 5; \
    const int cb = k0 & 511; \
    const int dy = rr / 3 - 1, dx = rr - 3 * (rr / 3) - 1; \
    const float* wp = g_wt + ((size_t)(k0 + fk) << 9) + m0 + fp; \
    float4 w0 = *reinterpret_cast<const float4*>(wp); \
    float4 w1 = *reinterpret_cast<const float4*>(wp + 4); \
    av[0]=w0.x; av[1]=w0.y; av[2]=w0.z; av[3]=w0.w; \
    av[4]=w1.x; av[5]=w1.y; av[6]=w1.z; av[7]=w1.w; \
    const int yy = ybase + dy; \
    const bool rok = (unsigned)yy < 64u; \
    const float* bp = xim + ((size_t)(cb + fk) << 12) + (yy << 6) + xbase + dx; \
    _Pragma("unroll") \
    for (int i = 0; i < 8; i++) { \
        int xx = xbase + dx + i; \
        bv[i] = (rok && (unsigned)xx < 64u) ? bp[i] : 0.f; \
    } } while (0)

#define CVSTORE(BUF) do { \
    float* SA = sm + (BUF) * BUF_F + fk * TPAD + fp; \
    float* SAl = SA + TILE_F; \
    float* SB = SA + 2 * TILE_F; \
    float* SBl = SA + 3 * TILE_F; \
    uint32_t h[8]; float l[8]; \
    _Pragma("unroll") \
    for (int i = 0; i < 8; i++) { h[i] = f2tf(av[i]); l[i] = av[i] - __uint_as_float(h[i]); } \
    *reinterpret_cast<uint4*>(SA) = make_uint4(h[0], h[1], h[2], h[3]); \
    *reinterpret_cast<uint4*>(SA + 4) = make_uint4(h[4], h[5], h[6], h[7]); \
    { uint32_t lt[8]; \
      _Pragma("unroll") for (int i = 0; i < 8; i++) lt[i] = f2tf(l[i]); \
      *reinterpret_cast<uint4*>(SAl) = make_uint4(lt[0], lt[1], lt[2], lt[3]); \
      *reinterpret_cast<uint4*>(SAl + 4) = make_uint4(lt[4], lt[5], lt[6], lt[7]); } \
    _Pragma("unroll") \
    for (int i = 0; i < 8; i++) { h[i] = f2tf(bv[i]); l[i] = bv[i] - __uint_as_float(h[i]); } \
    *reinterpret_cast<uint4*>(SB) = make_uint4(h[0], h[1], h[2], h[3]); \
    *reinterpret_cast<uint4*>(SB + 4) = make_uint4(h[4], h[5], h[6], h[7]); \
    { uint32_t lt[8]; \
      _Pragma("unroll") for (int i = 0; i < 8; i++) lt[i] = f2tf(l[i]); \
      *reinterpret_cast<uint4*>(SBl) = make_uint4(lt[0], lt[1], lt[2], lt[3]); \
      *reinterpret_cast<uint4*>(SBl + 4) = make_uint4(lt[4], lt[5], lt[6], lt[7]); } \
    } while (0)

    LOADG(0);
    CVSTORE(0);
    __syncthreads();

    int buf = 0;
    for (int ch = 0; ch < NCH; ch++) {
        const bool more = ch + 1 < NCH;
        if (more) LOADG(ch + 1);

        {
            const uint32_t* SA = reinterpret_cast<const uint32_t*>(sm + buf * BUF_F);
            const uint32_t* SAl = SA + TILE_F;
            const uint32_t* SB = SA + 2 * TILE_F;
            const uint32_t* SBl = SA + 3 * TILE_F;
            const int r0 = tk * TPAD;
            const int r4 = r0 + 4 * TPAD;
#pragma unroll
            for (int ks = 0; ks < 2; ks++) {
                const int ro = ks * 8 * TPAD;
                uint32_t bh[4][2], bl[4][2];
#pragma unroll
                for (int nf = 0; nf < 4; nf++) {
                    const int nb = wn * 32 + nf * 8 + g;
                    bh[nf][0] = SB[ro + r0 + nb];
                    bh[nf][1] = SB[ro + r4 + nb];
                    bl[nf][0] = SBl[ro + r0 + nb];
                    bl[nf][1] = SBl[ro + r4 + nb];
                }
#pragma unroll
                for (int mf = 0; mf < 4; mf++) {
                    const int mb = wm * 64 + mf * 16 + g;
                    uint32_t ah[4], al[4];
                    ah[0] = SA[ro + r0 + mb];     ah[1] = SA[ro + r0 + mb + 8];
                    ah[2] = SA[ro + r4 + mb];     ah[3] = SA[ro + r4 + mb + 8];
                    al[0] = SAl[ro + r0 + mb];    al[1] = SAl[ro + r0 + mb + 8];
                    al[2] = SAl[ro + r4 + mb];    al[3] = SAl[ro + r4 + mb + 8];
#pragma unroll
                    for (int nf = 0; nf < 4; nf++) {
                        float t[4];
                        MMA_TF32_Z(t, ah, bh[nf]);    // partial = Ahi*Bhi
                        MMA_TF32(t, ah, bl[nf]);      // + Ahi*Blo
                        MMA_TF32(t, al, bh[nf]);      // + Alo*Bhi
                        sum[mf][nf][0] += t[0];
                        sum[mf][nf][1] += t[1];
                        sum[mf][nf][2] += t[2];
                        sum[mf][nf][3] += t[3];
                    }
                }
            }
        }

        if (more) CVSTORE(buf ^ 1);
        __syncthreads();
        buf ^= 1;
    }

    // epilogue: bias + relu
    const int spb = n0 & 4095;
#pragma unroll
    for (int mf = 0; mf < 4; mf++) {
        const int m = m0 + wm * 64 + mf * 16 + g;
        const float bv0 = bias[m];
        const float bv1 = bias[m + 8];
        float* h0 = g_h + ((size_t)img * C_IN + m) * SP + spb;
        float* h1 = h0 + 8 * SP;
#pragma unroll
        for (int nf = 0; nf < 4; nf++) {
            const int nn = wn * 32 + nf * 8 + 2 * tk;
            float2 v0, v1;
            v0.x = fmaxf(sum[mf][nf][0] + bv0, 0.f);
            v0.y = fmaxf(sum[mf][nf][1] + bv0, 0.f);
            v1.x = fmaxf(sum[mf][nf][2] + bv1, 0.f);
            v1.y = fmaxf(sum[mf][nf][3] + bv1, 0.f);
            *reinterpret_cast<float2*>(h0 + nn) = v0;
            *reinterpret_cast<float2*>(h1 + nn) = v1;
        }
    }
}

// ===================== heads: 1x1 convs (18 score, 36 loc), transpose, softmax =====================
__global__ __launch_bounds__(128) void heads_kernel(
    const float* __restrict__ Ws, const float* __restrict__ bs,
    const float* __restrict__ Wl, const float* __restrict__ bl,
    float* __restrict__ out)
{
    __shared__ float Wt[54][64];
    const int tid = threadIdx.x;
    const int col = blockIdx.x * 128 + tid;
    const int img = col >> 12;
    const int sp = col & 4095;

    float acc[54];
#pragma unroll
    for (int o = 0; o < 54; o++) acc[o] = 0.f;

    for (int c0 = 0; c0 < C_IN; c0 += 64) {
        for (int i = tid; i < 54 * 64; i += 128) {
            int o = i >> 6, cc = i & 63;
            Wt[o][cc] = (o < 18) ? Ws[o * C_IN + c0 + cc] : Wl[(o - 18) * C_IN + c0 + cc];
        }
        __syncthreads();
        const float* hp = g_h + (size_t)img * C_IN * SP + (size_t)c0 * SP + sp;
#pragma unroll 4
        for (int cc = 0; cc < 64; cc++) {
            float xv = hp[(size_t)cc * SP];
#pragma unroll
            for (int o = 0; o < 54; o++) acc[o] += xv * Wt[o][cc];
        }
        __syncthreads();
    }

    const size_t base9 = (size_t)img * NANCH + (size_t)sp * 9;
#pragma unroll
    for (int o = 0; o < 18; o++) {
        float v = acc[o] + bs[o];
        out[OFF_SC + (base9 + (o >> 1)) * 2 + (o & 1)] = v;
    }
#pragma unroll
    for (int o = 0; o < 36; o++) {
        float v = acc[18 + o] + bl[o];
        out[OFF_LOC + (base9 + (o >> 2)) * 4 + (o & 3)] = v;
    }
#pragma unroll
    for (int a = 0; a < 9; a++) {
        float s0 = acc[2 * a] + bs[2 * a];
        float s1 = acc[2 * a + 1] + bs[2 * a + 1];
        float m = fmaxf(s0, s1);
        float e0 = expf(s0 - m), e1 = expf(s1 - m);
        g_fg[base9 + a] = e1 / (e0 + e1);
    }
}

// ===================== loc2bbox + clip + min-size + sort keys =====================
__global__ void boxes_kernel(const float* __restrict__ locs,
                             const int* __restrict__ imh_p, const int* __restrict__ imw_p)
{
    int t = blockIdx.x * blockDim.x + threadIdx.x;
    if (t >= N_IMG * NANCH) return;
    int img = t / NANCH;
    int li = t - img * NANCH;

    int pix = li / 9;
    int a = li - pix * 9;
    int y = pix >> 6, x = pix & 63;
    int ri = a / 3, si = a - ri * 3;
    float ratio = (ri == 0) ? 0.5f : ((ri == 1) ? 1.0f : 2.0f);
    float scl = (si == 0) ? 8.f : ((si == 1) ? 16.f : 32.f);
    float hs = (16.f * scl) * sqrtf(ratio);
    float ws = (16.f * scl) * sqrtf(1.0f / ratio);
    float sy = (float)(y * 16), sx = (float)(x * 16);
    float ay1 = sy + (8.f - hs * 0.5f);
    float ax1 = sx + (8.f - ws * 0.5f);
    float ay2 = sy + (8.f + hs * 0.5f);
    float ax2 = sx + (8.f + ws * 0.5f);

    const float* lp = locs + ((size_t)img * NANCH + li) * 4;
    float dy = lp[0], dx = lp[1], dh = lp[2], dw = lp[3];
    float ah = ay2 - ay1, aw = ax2 - ax1;
    float acy = ay1 + 0.5f * ah, acx = ax1 + 0.5f * aw;
    float cy = dy * ah + acy, cx = dx * aw + acx;
    float hb = expf(dh) * ah, wb = expf(dw) * aw;

    float imh = read_scalar(imh_p);
    float imw = read_scalar(imw_p);
    float y1 = fminf(fmaxf(cy - 0.5f * hb, 0.f), imh);
    float x1 = fminf(fmaxf(cx - 0.5f * wb, 0.f), imw);
    float y2 = fminf(fmaxf(cy + 0.5f * hb, 0.f), imh);
    float x2 = fminf(fmaxf(cx + 0.5f * wb, 0.f), imw);

    float* bp = g_boxes + ((size_t)img * NANCH + li) * 4;
    bp[0] = y1; bp[1] = x1; bp[2] = y2; bp[3] = x2;

    bool valid = ((y2 - y1) >= 16.f) && ((x2 - x1) >= 16.f);
    float s = valid ? g_fg[(size_t)img * NANCH + li] : -INFINITY;
    unsigned u = __float_as_uint(s);
    unsigned desc = (u & 0x80000000u) ? u : (~u & 0x7FFFFFFFu);   // ascending key = descending score
    g_keys[(size_t)img * NS + li] = ((unsigned long long)desc << 32) | (unsigned)li;
}

// ===================== bitonic sort (per-image 65536 keys, ascending) =====================
__global__ __launch_bounds__(512) void sort_local8k()
{
    extern __shared__ unsigned long long s[];
    const int base = blockIdx.x * 8192;
    for (int i = threadIdx.x; i < 8192; i += 512) s[i] = g_keys[base + i];
    __syncthreads();
    for (int k = 2; k <= 8192; k <<= 1) {
        for (int j = k >> 1; j > 0; j >>= 1) {
            for (int t = threadIdx.x; t < 4096; t += 512) {
                int i = ((t & ~(j - 1)) << 1) | (t & (j - 1));
                int l = i | j;
                bool up = (((base + i) & k) == 0);
                unsigned long long va = s[i], vb = s[l];
                if ((va > vb) == up) { s[i] = vb; s[l] = va; }
            }
            __syncthreads();
        }
    }
    for (int i = threadIdx.x; i < 8192; i += 512) g_keys[base + i] = s[i];
}

__global__ void sort_global(int k, int j)
{
    int t = blockIdx.x * blockDim.x + threadIdx.x;  // 4*32768
    int img = t >> 15, tt = t & 32767;
    int i = ((tt & ~(j - 1)) << 1) | (tt & (j - 1));
    int l = i | j;
    unsigned long long* p = g_keys + (size_t)img * NS;
    bool up = ((i & k) == 0);
    unsigned long long va = p[i], vb = p[l];
    if ((va > vb) == up) { p[i] = vb; p[l] = va; }
}

__global__ __launch_bounds__(512) void merge_local8k(int k)
{
    extern __shared__ unsigned long long s[];
    const int base = blockIdx.x * 8192;
    for (int i = threadIdx.x; i < 8192; i += 512) s[i] = g_keys[base + i];
    __syncthreads();
    bool up = (((base & (NS - 1)) & k) == 0);
    for (int j = 4096; j > 0; j >>= 1) {
        for (int t = threadIdx.x; t < 4096; t += 512) {
            int i = ((t & ~(j - 1)) << 1) | (t & (j - 1));
            int l = i | j;
            unsigned long long va = s[i], vb = s[l];
            if ((va > vb) == up) { s[i] = vb; s[l] = va; }
        }
        __syncthreads();
    }
    for (int i = threadIdx.x; i < 8192; i += 512) g_keys[base + i] = s[i];
}

// ===================== gather top-3000 =====================
__global__ void gather_kernel()
{
    int t = blockIdx.x * blockDim.x + threadIdx.x;
    if (t >= N_IMG * PRE) return;
    int img = t / PRE, r = t - img * PRE;
    unsigned long long key = g_keys[(size_t)img * NS + r];
    int li = (int)(key & 0xFFFFFFFFull);
    unsigned desc = (unsigned)(key >> 32);
    g_selfin[img * PRE + r] = (desc < 0xFF800000u) ? 1 : 0;  // finite score
    float4 b = *reinterpret_cast<const float4*>(&g_boxes[((size_t)img * NANCH + li) * 4]);
    *reinterpret_cast<float4*>(&g_selbox[((size_t)img * PRE + r) * 4]) = b;
}

// ===================== IoU > 0.7 bitmask =====================
__global__ void iou_kernel()
{
    int t = blockIdx.x * blockDim.x + threadIdx.x;
    if (t >= N_IMG * PRE * NWORDS) return;
    int img = t / (PRE * NWORDS);
    int rem = t - img * (PRE * NWORDS);
    int i = rem / NWORDS;
    int w = rem - i * NWORDS;
    const float* B = g_selbox + (size_t)img * PRE * 4;
    float4 bi = *reinterpret_cast<const float4*>(B + (size_t)i * 4);
    float ai = (bi.z - bi.x) * (bi.w - bi.y);
    unsigned bits = 0;
    int j0 = w * 32;
#pragma unroll 4
    for (int jj = 0; jj < 32; jj++) {
        int j = j0 + jj;
        if (j >= PRE) break;
        float4 bj = *reinterpret_cast<const float4*>(B + (size_t)j * 4);
        float yy1 = fmaxf(bi.x, bj.x), xx1 = fmaxf(bi.y, bj.y);
        float yy2 = fminf(bi.z, bj.z), xx2 = fminf(bi.w, bj.w);
        float ih = fmaxf(yy2 - yy1, 0.f), iw = fmaxf(xx2 - xx1, 0.f);
        float inter = ih * iw;
        float aj = (bj.z - bj.x) * (bj.w - bj.y);
        float uni = ai + aj - inter;
        float iou = (uni > 0.f) ? (inter / uni) : 0.f;
        if (iou > 0.7f) bits |= (1u << jj);
    }
    g_mask[((size_t)img * PRE + i) * NWORDS + w] = bits;
}

// ===================== sequential greedy NMS with 8-deep row prefetch =====================
__global__ void nms_kernel(float* __restrict__ out)
{
    const int img = blockIdx.x;
    const int lane = threadIdx.x;
    __shared__ int kept[POST];
    __shared__ int s_nk;
    unsigned r0 = 0, r1 = 0, r2 = 0;   // lane owns removed-words [3*lane .. 3*lane+2]
    int nk = 0;
    const unsigned* M = g_mask + (size_t)img * PRE * NWORDS;
    const int* fin = g_selfin + img * PRE;
    const int b0 = lane * 3;
    const bool v0 = (b0 < NWORDS), v1 = (b0 + 1 < NWORDS), v2 = (b0 + 2 < NWORDS);

    unsigned p0[8], p1[8], p2[8];      // prefetched rows i..i+7
#pragma unroll
    for (int s = 0; s < 8; s++) {
        const unsigned* row = M + (size_t)s * NWORDS + b0;
        p0[s] = v0 ? __ldg(row) : 0u;
        p1[s] = v1 ? __ldg(row + 1) : 0u;
        p2[s] = v2 ? __ldg(row + 2) : 0u;
    }

    for (int ib = 0; ib < PRE; ib += 8) {
#pragma unroll
        for (int s = 0; s < 8; s++) {
            int i = ib + s;
            int wi = i >> 5;
            int owner = wi / 3, sub = wi - owner * 3;
            unsigned myw = (sub == 0) ? r0 : ((sub == 1) ? r1 : r2);
            unsigned word = __shfl_sync(0xffffffffu, myw, owner);
            if (!((word >> (i & 31)) & 1u)) {
                if (lane == 0 && fin[i] && nk < POST) { kept[nk] = i; nk++; }
                r0 |= p0[s]; r1 |= p1[s]; r2 |= p2[s];
            }
            int ip = i + 8;
            if (ip < PRE) {
                const unsigned* row = M + (size_t)ip * NWORDS + b0;
                p0[s] = v0 ? __ldg(row) : 0u;
                p1[s] = v1 ? __ldg(row + 1) : 0u;
                p2[s] = v2 ? __ldg(row + 2) : 0u;
            }
        }
        int cnt = __shfl_sync(0xffffffffu, nk, 0);
        if (cnt >= POST) break;
    }
    if (lane == 0) s_nk = nk;
    __syncwarp();
    int NK = s_nk;

    for (int r = lane; r < POST; r += 32) {
        float4 b = make_float4(0.f, 0.f, 0.f, 0.f);
        float v = 0.f;
        if (r < NK) {
            b = *reinterpret_cast<const float4*>(&g_selbox[((size_t)img * PRE + kept[r]) * 4]);
            v = 1.f;
        }
        float* rp = out + OFF_ROI + ((size_t)img * POST + r) * 4;
        rp[0] = b.x; rp[1] = b.y; rp[2] = b.z; rp[3] = b.w;
        out[OFF_VAL + img * POST + r] = v;
    }
}

// ===================== launch =====================
extern "C" void kernel_launch(void* const* d_in, const int* in_sizes, int n_in,
                              void* d_out, int out_size)
{
    const float* x  = (const float*)d_in[0];
    const float* W1 = (const float*)d_in[1];
    const float* b1 = (const float*)d_in[2];
    const float* Ws = (const float*)d_in[3];
    const float* bs = (const float*)d_in[4];
    const float* Wl = (const float*)d_in[5];
    const float* bl = (const float*)d_in[6];
    const int* imh  = (const int*)d_in[7];
    const int* imw  = (const int*)d_in[8];
    float* out = (float*)d_out;

    cudaFuncSetAttribute(sort_local8k, cudaFuncAttributeMaxDynamicSharedMemorySize, 65536);
    cudaFuncSetAttribute(merge_local8k, cudaFuncAttributeMaxDynamicSharedMemorySize, 65536);
    cudaFuncSetAttribute(conv3x3_kernel, cudaFuncAttributeMaxDynamicSharedMemorySize, CONV_SMEM_B);

    // conv is the 4th launch (the one ncu profiles)
    anchors_kernel<<<(NANCH + 255) / 256, 256>>>(out + OFF_ANC);
    pad_keys_kernel<<<(N_IMG * (NS - NANCH) + 255) / 256, 256>>>();
    wtrans_kernel<<<(KTOT * C_IN + 255) / 256, 256>>>(W1);

    conv3x3_kernel<<<dim3(128, 4), 256, CONV_SMEM_B>>>(x, b1);
    heads_kernel<<<128, 128>>>(Ws, bs, Wl, bl, out);
    boxes_kernel<<<(N_IMG * NANCH + 255) / 256, 256>>>(out + OFF_LOC, imh, imw);

    sort_local8k<<<32, 512, 65536>>>();
    for (int k = 16384; k <= 65536; k <<= 1) {
        for (int j = k >> 1; j >= 8192; j >>= 1)
            sort_global<<<512, 256>>>(k, j);
        merge_local8k<<<32, 512, 65536>>>(k);
    }

    gather_kernel<<<(N_IMG * PRE + 255) / 256, 256>>>();
    iou_kernel<<<(N_IMG * PRE * NWORDS + 255) / 256, 256>>>();
    nms_kernel<<<4, 32>>>(out);
}

// round 13
// speedup vs baseline: 1.9275x; 1.0006x over previous
#include <cuda_runtime.h>
#include <math.h>
#include <stdint.h>

#define N_IMG 4
#define C_IN 512
#define SP 4096              // 64*64 per image
#define KTOT 4608            // 512*9
#define NANCH 36864          // 4096*9
#define NS 65536             // padded sort size per image
#define PRE 3000
#define POST 300
#define NWORDS 94            // ceil(3000/32)

// output layout (concatenated float32, reference return order)
#define OFF_LOC 0
#define OFF_SC  589824
#define OFF_ROI 884736
#define OFF_VAL 889536
#define OFF_ANC 890736

// -------- scratch (static device globals; no allocation) --------
__device__ float g_h[N_IMG * C_IN * SP];          // conv1 output, NCHW
__device__ float g_wt[KTOT * C_IN];               // W1 transposed, K reordered r*512+c
__device__ float g_fg[N_IMG * NANCH];             // softmax fg scores
__device__ float g_boxes[N_IMG * NANCH * 4];      // decoded+clipped boxes
__device__ unsigned long long g_keys[N_IMG * NS]; // sort keys
__device__ float g_selbox[N_IMG * PRE * 4];       // top-3000 boxes
__device__ int   g_selfin[N_IMG * PRE];           // finite-score flag
__device__ unsigned g_mask[N_IMG * PRE * NWORDS]; // iou>0.7 bitmask rows

__device__ __forceinline__ float read_scalar(const int* p) {
    int iv = *p;
    if (iv > 0 && iv < (1 << 24)) return (float)iv;
    return *reinterpret_cast<const float*>(p);
}

__device__ __forceinline__ uint32_t f2tf(float f) {
    uint32_t r;
    asm("cvt.rna.tf32.f32 %0, %1;" : "=r"(r) : "f"(f));
    return r;
}

// chained MMA: c += a*b  (NON-volatile: pure register op, lets ptxas
// interleave the independent nf chains to hide MMA latency)
#define MMA_TF32(c, a, b) \
    asm("mma.sync.aligned.m16n8k8.row.col.f32.tf32.tf32.f32 " \
        "{%0,%1,%2,%3},{%4,%5,%6,%7},{%8,%9},{%0,%1,%2,%3};" \
        : "+f"((c)[0]), "+f"((c)[1]), "+f"((c)[2]), "+f"((c)[3]) \
        : "r"((a)[0]), "r"((a)[1]), "r"((a)[2]), "r"((a)[3]), \
          "r"((b)[0]), "r"((b)[1]))

// fresh MMA: c = a*b + 0   (d != c; kills accumulator bias chains)
#define MMA_TF32_Z(c, a, b) \
    asm("mma.sync.aligned.m16n8k8.row.col.f32.tf32.tf32.f32 " \
        "{%0,%1,%2,%3},{%4,%5,%6,%7},{%8,%9},{%10,%11,%12,%13};" \
        : "=f"((c)[0]), "=f"((c)[1]), "=f"((c)[2]), "=f"((c)[3]) \
        : "r"((a)[0]), "r"((a)[1]), "r"((a)[2]), "r"((a)[3]), \
          "r"((b)[0]), "r"((b)[1]), \
          "f"(0.f), "f"(0.f), "f"(0.f), "f"(0.f))

// ===================== pre-conv kernels (conv must be 4th launch for ncu) =====================
__global__ void anchors_kernel(float* __restrict__ anch_out)
{
    int li = blockIdx.x * blockDim.x + threadIdx.x;
    if (li >= NANCH) return;
    int pix = li / 9;
    int a = li - pix * 9;
    int y = pix >> 6, x = pix & 63;
    int ri = a / 3, si = a - ri * 3;
    float ratio = (ri == 0) ? 0.5f : ((ri == 1) ? 1.0f : 2.0f);
    float scl = (si == 0) ? 8.f : ((si == 1) ? 16.f : 32.f);
    float hs = (16.f * scl) * sqrtf(ratio);
    float ws = (16.f * scl) * sqrtf(1.0f / ratio);
    float sy = (float)(y * 16), sx = (float)(x * 16);
    float* ap = anch_out + (size_t)li * 4;
    ap[0] = sy + (8.f - hs * 0.5f);
    ap[1] = sx + (8.f - ws * 0.5f);
    ap[2] = sy + (8.f + hs * 0.5f);
    ap[3] = sx + (8.f + ws * 0.5f);
}

__global__ void pad_keys_kernel()
{
    int t = blockIdx.x * blockDim.x + threadIdx.x;
    int per = NS - NANCH;
    if (t >= N_IMG * per) return;
    int img = t / per, li = NANCH + (t - img * per);
    g_keys[(size_t)img * NS + li] = 0xFFFFFFFFFFFFFFFFull;
}

// W1[m][c*9+r]  ->  g_wt[(r*512+c)*512 + m]
__global__ void wtrans_kernel(const float* __restrict__ W1)
{
    int t = blockIdx.x * blockDim.x + threadIdx.x;
    if (t >= KTOT * C_IN) return;
    int k = t >> 9, m = t & 511;
    int rr = k >> 9, c = k & 511;
    g_wt[t] = W1[(size_t)m * KTOT + c * 9 + rr];
}

// ===================== conv 3x3 via mma.sync tf32 (3-pass hi/lo, segmented accum) =====================
// D[m][n] = sum_k W[m][k]*im2col[n][k], K reordered k = r*512 + c (tap-outer).
// CTA tile 128x128, 8 warps of 64x32; K chunk 16, double-buffered smem.
// Per 8-k halfchunk per 16x8 tile: 3 MMAs on a zero-seeded c-fragment, then
// RN FADD into persistent fp32 accumulators (bounds tensor-core accum error).
#define TPAD 136
#define TILE_F (16 * TPAD)                 // 2176 floats per tile
#define BUF_F (4 * TILE_F)                 // Ahi, Alo, Bhi, Blo
#define CONV_SMEM_B (2 * BUF_F * 4)        // 69632 bytes
#define NCH 288

__global__ __launch_bounds__(256, 2) void conv3x3_kernel(
    const float* __restrict__ x, const float* __restrict__ bias)
{
    extern __shared__ float sm[];
    const int tid = threadIdx.x;
    const int n0 = blockIdx.x * 128;
    const int m0 = blockIdx.y * 128;
    const int wid = tid >> 5, lane = tid & 31;
    const int g = lane >> 2, tk = lane & 3;
    const int wm = wid >> 2, wn = wid & 3;

    // fill coordinates
    const int fk = tid >> 4;              // k row 0..15
    const int fp = (tid & 15) * 8;        // col base 0..120
    const int img = n0 >> 12;
    const int nb_ = n0 + fp;
    const int ybase = (nb_ >> 6) & 63;
    const int xbase = nb_ & 63;
    const float* xim = x + (size_t)img * (C_IN * SP);

    float sum[4][4][4];
#pragma unroll
    for (int a = 0; a < 4; a++)
#pragma unroll
        for (int b = 0; b < 4; b++)
#pragma unroll
            for (int c = 0; c < 4; c++) sum[a][b][c] = 0.f;

    float av[8], bv[8];

#define LOADG(CH) do { \
    const int k0 = (CH) << 4; \
    const int rr = (CH) >> 5; \
    const int cb = k0 & 511; \
    const int dy = rr / 3 - 1, dx = rr - 3 * (rr / 3) - 1; \
    const float* wp = g_wt + ((size_t)(k0 + fk) << 9) + m0 + fp; \
    float4 w0 = *reinterpret_cast<const float4*>(wp); \
    float4 w1 = *reinterpret_cast<const float4*>(wp + 4); \
    av[0]=w0.x; av[1]=w0.y; av[2]=w0.z; av[3]=w0.w; \
    av[4]=w1.x; av[5]=w1.y; av[6]=w1.z; av[7]=w1.w; \
    const int yy = ybase + dy; \
    const bool rok = (unsigned)yy < 64u; \
    const float* bp = xim + ((size_t)(cb + fk) << 12) + (yy << 6) + xbase + dx; \
    _Pragma("unroll") \
    for (int i = 0; i < 8; i++) { \
        int xx = xbase + dx + i; \
        bv[i] = (rok && (unsigned)xx < 64u) ? bp[i] : 0.f; \
    } } while (0)

#define CVSTORE(BUF) do { \
    float* SA = sm + (BUF) * BUF_F + fk * TPAD + fp; \
    float* SAl = SA + TILE_F; \
    float* SB = SA + 2 * TILE_F; \
    float* SBl = SA + 3 * TILE_F; \
    uint32_t h[8]; float l[8]; \
    _Pragma("unroll") \
    for (int i = 0; i < 8; i++) { h[i] = f2tf(av[i]); l[i] = av[i] - __uint_as_float(h[i]); } \
    *reinterpret_cast<uint4*>(SA) = make_uint4(h[0], h[1], h[2], h[3]); \
    *reinterpret_cast<uint4*>(SA + 4) = make_uint4(h[4], h[5], h[6], h[7]); \
    { uint32_t lt[8]; \
      _Pragma("unroll") for (int i = 0; i < 8; i++) lt[i] = f2tf(l[i]); \
      *reinterpret_cast<uint4*>(SAl) = make_uint4(lt[0], lt[1], lt[2], lt[3]); \
      *reinterpret_cast<uint4*>(SAl + 4) = make_uint4(lt[4], lt[5], lt[6], lt[7]); } \
    _Pragma("unroll") \
    for (int i = 0; i < 8; i++) { h[i] = f2tf(bv[i]); l[i] = bv[i] - __uint_as_float(h[i]); } \
    *reinterpret_cast<uint4*>(SB) = make_uint4(h[0], h[1], h[2], h[3]); \
    *reinterpret_cast<uint4*>(SB + 4) = make_uint4(h[4], h[5], h[6], h[7]); \
    { uint32_t lt[8]; \
      _Pragma("unroll") for (int i = 0; i < 8; i++) lt[i] = f2tf(l[i]); \
      *reinterpret_cast<uint4*>(SBl) = make_uint4(lt[0], lt[1], lt[2], lt[3]); \
      *reinterpret_cast<uint4*>(SBl + 4) = make_uint4(lt[4], lt[5], lt[6], lt[7]); } \
    } while (0)

    LOADG(0);
    CVSTORE(0);
    __syncthreads();

    int buf = 0;
    for (int ch = 0; ch < NCH; ch++) {
        const bool more = ch + 1 < NCH;
        if (more) LOADG(ch + 1);

        {
            const uint32_t* SA = reinterpret_cast<const uint32_t*>(sm + buf * BUF_F);
            const uint32_t* SAl = SA + TILE_F;
            const uint32_t* SB = SA + 2 * TILE_F;
            const uint32_t* SBl = SA + 3 * TILE_F;
            const int r0 = tk * TPAD;
            const int r4 = r0 + 4 * TPAD;
#pragma unroll
            for (int ks = 0; ks < 2; ks++) {
                const int ro = ks * 8 * TPAD;
                uint32_t bh[4][2], bl[4][2];
#pragma unroll
                for (int nf = 0; nf < 4; nf++) {
                    const int nb = wn * 32 + nf * 8 + g;
                    bh[nf][0] = SB[ro + r0 + nb];
                    bh[nf][1] = SB[ro + r4 + nb];
                    bl[nf][0] = SBl[ro + r0 + nb];
                    bl[nf][1] = SBl[ro + r4 + nb];
                }
#pragma unroll
                for (int mf = 0; mf < 4; mf++) {
                    const int mb = wm * 64 + mf * 16 + g;
                    uint32_t ah[4], al[4];
                    ah[0] = SA[ro + r0 + mb];     ah[1] = SA[ro + r0 + mb + 8];
                    ah[2] = SA[ro + r4 + mb];     ah[3] = SA[ro + r4 + mb + 8];
                    al[0] = SAl[ro + r0 + mb];    al[1] = SAl[ro + r0 + mb + 8];
                    al[2] = SAl[ro + r4 + mb];    al[3] = SAl[ro + r4 + mb + 8];
#pragma unroll
                    for (int nf = 0; nf < 4; nf++) {
                        float t[4];
                        MMA_TF32_Z(t, ah, bh[nf]);    // partial = Ahi*Bhi
                        MMA_TF32(t, ah, bl[nf]);      // + Ahi*Blo
                        MMA_TF32(t, al, bh[nf]);      // + Alo*Bhi
                        sum[mf][nf][0] += t[0];
                        sum[mf][nf][1] += t[1];
                        sum[mf][nf][2] += t[2];
                        sum[mf][nf][3] += t[3];
                    }
                }
            }
        }

        if (more) CVSTORE(buf ^ 1);
        __syncthreads();
        buf ^= 1;
    }

    // epilogue: bias + relu
    const int spb = n0 & 4095;
#pragma unroll
    for (int mf = 0; mf < 4; mf++) {
        const int m = m0 + wm * 64 + mf * 16 + g;
        const float bv0 = bias[m];
        const float bv1 = bias[m + 8];
        float* h0 = g_h + ((size_t)img * C_IN + m) * SP + spb;
        float* h1 = h0 + 8 * SP;
#pragma unroll
        for (int nf = 0; nf < 4; nf++) {
            const int nn = wn * 32 + nf * 8 + 2 * tk;
            float2 v0, v1;
            v0.x = fmaxf(sum[mf][nf][0] + bv0, 0.f);
            v0.y = fmaxf(sum[mf][nf][1] + bv0, 0.f);
            v1.x = fmaxf(sum[mf][nf][2] + bv1, 0.f);
            v1.y = fmaxf(sum[mf][nf][3] + bv1, 0.f);
            *reinterpret_cast<float2*>(h0 + nn) = v0;
            *reinterpret_cast<float2*>(h1 + nn) = v1;
        }
    }
}

// ===================== heads: 1x1 convs (18 score, 36 loc), transpose, softmax =====================
__global__ __launch_bounds__(128) void heads_kernel(
    const float* __restrict__ Ws, const float* __restrict__ bs,
    const float* __restrict__ Wl, const float* __restrict__ bl,
    float* __restrict__ out)
{
    __shared__ float Wt[54][64];
    const int tid = threadIdx.x;
    const int col = blockIdx.x * 128 + tid;
    const int img = col >> 12;
    const int sp = col & 4095;

    float acc[54];
#pragma unroll
    for (int o = 0; o < 54; o++) acc[o] = 0.f;

    for (int c0 = 0; c0 < C_IN; c0 += 64) {
        for (int i = tid; i < 54 * 64; i += 128) {
            int o = i >> 6, cc = i & 63;
            Wt[o][cc] = (o < 18) ? Ws[o * C_IN + c0 + cc] : Wl[(o - 18) * C_IN + c0 + cc];
        }
        __syncthreads();
        const float* hp = g_h + (size_t)img * C_IN * SP + (size_t)c0 * SP + sp;
#pragma unroll 4
        for (int cc = 0; cc < 64; cc++) {
            float xv = hp[(size_t)cc * SP];
#pragma unroll
            for (int o = 0; o < 54; o++) acc[o] += xv * Wt[o][cc];
        }
        __syncthreads();
    }

    const size_t base9 = (size_t)img * NANCH + (size_t)sp * 9;
#pragma unroll
    for (int o = 0; o < 18; o++) {
        float v = acc[o] + bs[o];
        out[OFF_SC + (base9 + (o >> 1)) * 2 + (o & 1)] = v;
    }
#pragma unroll
    for (int o = 0; o < 36; o++) {
        float v = acc[18 + o] + bl[o];
        out[OFF_LOC + (base9 + (o >> 2)) * 4 + (o & 3)] = v;
    }
#pragma unroll
    for (int a = 0; a < 9; a++) {
        float s0 = acc[2 * a] + bs[2 * a];
        float s1 = acc[2 * a + 1] + bs[2 * a + 1];
        float m = fmaxf(s0, s1);
        float e0 = expf(s0 - m), e1 = expf(s1 - m);
        g_fg[base9 + a] = e1 / (e0 + e1);
    }
}

// ===================== loc2bbox + clip + min-size + sort keys =====================
__global__ void boxes_kernel(const float* __restrict__ locs,
                             const int* __restrict__ imh_p, const int* __restrict__ imw_p)
{
    int t = blockIdx.x * blockDim.x + threadIdx.x;
    if (t >= N_IMG * NANCH) return;
    int img = t / NANCH;
    int li = t - img * NANCH;

    int pix = li / 9;
    int a = li - pix * 9;
    int y = pix >> 6, x = pix & 63;
    int ri = a / 3, si = a - ri * 3;
    float ratio = (ri == 0) ? 0.5f : ((ri == 1) ? 1.0f : 2.0f);
    float scl = (si == 0) ? 8.f : ((si == 1) ? 16.f : 32.f);
    float hs = (16.f * scl) * sqrtf(ratio);
    float ws = (16.f * scl) * sqrtf(1.0f / ratio);
    float sy = (float)(y * 16), sx = (float)(x * 16);
    float ay1 = sy + (8.f - hs * 0.5f);
    float ax1 = sx + (8.f - ws * 0.5f);
    float ay2 = sy + (8.f + hs * 0.5f);
    float ax2 = sx + (8.f + ws * 0.5f);

    const float* lp = locs + ((size_t)img * NANCH + li) * 4;
    float dy = lp[0], dx = lp[1], dh = lp[2], dw = lp[3];
    float ah = ay2 - ay1, aw = ax2 - ax1;
    float acy = ay1 + 0.5f * ah, acx = ax1 + 0.5f * aw;
    float cy = dy * ah + acy, cx = dx * aw + acx;
    float hb = expf(dh) * ah, wb = expf(dw) * aw;

    float imh = read_scalar(imh_p);
    float imw = read_scalar(imw_p);
    float y1 = fminf(fmaxf(cy - 0.5f * hb, 0.f), imh);
    float x1 = fminf(fmaxf(cx - 0.5f * wb, 0.f), imw);
    float y2 = fminf(fmaxf(cy + 0.5f * hb, 0.f), imh);
    float x2 = fminf(fmaxf(cx + 0.5f * wb, 0.f), imw);

    float* bp = g_boxes + ((size_t)img * NANCH + li) * 4;
    bp[0] = y1; bp[1] = x1; bp[2] = y2; bp[3] = x2;

    bool valid = ((y2 - y1) >= 16.f) && ((x2 - x1) >= 16.f);
    float s = valid ? g_fg[(size_t)img * NANCH + li] : -INFINITY;
    unsigned u = __float_as_uint(s);
    unsigned desc = (u & 0x80000000u) ? u : (~u & 0x7FFFFFFFu);   // ascending key = descending score
    g_keys[(size_t)img * NS + li] = ((unsigned long long)desc << 32) | (unsigned)li;
}

// ===================== bitonic sort (per-image 65536 keys, ascending) =====================
__global__ __launch_bounds__(512) void sort_local8k()
{
    extern __shared__ unsigned long long s[];
    const int base = blockIdx.x * 8192;
    for (int i = threadIdx.x; i < 8192; i += 512) s[i] = g_keys[base + i];
    __syncthreads();
    for (int k = 2; k <= 8192; k <<= 1) {
        for (int j = k >> 1; j > 0; j >>= 1) {
            for (int t = threadIdx.x; t < 4096; t += 512) {
                int i = ((t & ~(j - 1)) << 1) | (t & (j - 1));
                int l = i | j;
                bool up = (((base + i) & k) == 0);
                unsigned long long va = s[i], vb = s[l];
                if ((va > vb) == up) { s[i] = vb; s[l] = va; }
            }
            __syncthreads();
        }
    }
    for (int i = threadIdx.x; i < 8192; i += 512) g_keys[base + i] = s[i];
}

__global__ void sort_global(int k, int j)
{
    int t = blockIdx.x * blockDim.x + threadIdx.x;  // 4*32768
    int img = t >> 15, tt = t & 32767;
    int i = ((tt & ~(j - 1)) << 1) | (tt & (j - 1));
    int l = i | j;
    unsigned long long* p = g_keys + (size_t)img * NS;
    bool up = ((i & k) == 0);
    unsigned long long va = p[i], vb = p[l];
    if ((va > vb) == up) { p[i] = vb; p[l] = va; }
}

__global__ __launch_bounds__(512) void merge_local8k(int k)
{
    extern __shared__ unsigned long long s[];
    const int base = blockIdx.x * 8192;
    for (int i = threadIdx.x; i < 8192; i += 512) s[i] = g_keys[base + i];
    __syncthreads();
    bool up = (((base & (NS - 1)) & k) == 0);
    for (int j = 4096; j > 0; j >>= 1) {
        for (int t = threadIdx.x; t < 4096; t += 512) {
            int i = ((t & ~(j - 1)) << 1) | (t & (j - 1));
            int l = i | j;
            unsigned long long va = s[i], vb = s[l];
            if ((va > vb) == up) { s[i] = vb; s[l] = va; }
        }
        __syncthreads();
    }
    for (int i = threadIdx.x; i < 8192; i += 512) g_keys[base + i] = s[i];
}

// ===================== gather top-3000 =====================
__global__ void gather_kernel()
{
    int t = blockIdx.x * blockDim.x + threadIdx.x;
    if (t >= N_IMG * PRE) return;
    int img = t / PRE, r = t - img * PRE;
    unsigned long long key = g_keys[(size_t)img * NS + r];
    int li = (int)(key & 0xFFFFFFFFull);
    unsigned desc = (unsigned)(key >> 32);
    g_selfin[img * PRE + r] = (desc < 0xFF800000u) ? 1 : 0;  // finite score
    float4 b = *reinterpret_cast<const float4*>(&g_boxes[((size_t)img * NANCH + li) * 4]);
    *reinterpret_cast<float4*>(&g_selbox[((size_t)img * PRE + r) * 4]) = b;
}

// ===================== IoU > 0.7 bitmask =====================
__global__ void iou_kernel()
{
    int t = blockIdx.x * blockDim.x + threadIdx.x;
    if (t >= N_IMG * PRE * NWORDS) return;
    int img = t / (PRE * NWORDS);
    int rem = t - img * (PRE * NWORDS);
    int i = rem / NWORDS;
    int w = rem - i * NWORDS;
    const float* B = g_selbox + (size_t)img * PRE * 4;
    float4 bi = *reinterpret_cast<const float4*>(B + (size_t)i * 4);
    float ai = (bi.z - bi.x) * (bi.w - bi.y);
    unsigned bits = 0;
    int j0 = w * 32;
#pragma unroll 4
    for (int jj = 0; jj < 32; jj++) {
        int j = j0 + jj;
        if (j >= PRE) break;
        float4 bj = *reinterpret_cast<const float4*>(B + (size_t)j * 4);
        float yy1 = fmaxf(bi.x, bj.x), xx1 = fmaxf(bi.y, bj.y);
        float yy2 = fminf(bi.z, bj.z), xx2 = fminf(bi.w, bj.w);
        float ih = fmaxf(yy2 - yy1, 0.f), iw = fmaxf(xx2 - xx1, 0.f);
        float inter = ih * iw;
        float aj = (bj.z - bj.x) * (bj.w - bj.y);
        float uni = ai + aj - inter;
        float iou = (uni > 0.f) ? (inter / uni) : 0.f;
        if (iou > 0.7f) bits |= (1u << jj);
    }
    g_mask[((size_t)img * PRE + i) * NWORDS + w] = bits;
}

// ===================== sequential greedy NMS with 8-deep row prefetch =====================
__global__ void nms_kernel(float* __restrict__ out)
{
    const int img = blockIdx.x;
    const int lane = threadIdx.x;
    __shared__ int kept[POST];
    __shared__ int s_nk;
    unsigned r0 = 0, r1 = 0, r2 = 0;   // lane owns removed-words [3*lane .. 3*lane+2]
    int nk = 0;
    const unsigned* M = g_mask + (size_t)img * PRE * NWORDS;
    const int* fin = g_selfin + img * PRE;
    const int b0 = lane * 3;
    const bool v0 = (b0 < NWORDS), v1 = (b0 + 1 < NWORDS), v2 = (b0 + 2 < NWORDS);

    unsigned p0[8], p1[8], p2[8];      // prefetched rows i..i+7
#pragma unroll
    for (int s = 0; s < 8; s++) {
        const unsigned* row = M + (size_t)s * NWORDS + b0;
        p0[s] = v0 ? __ldg(row) : 0u;
        p1[s] = v1 ? __ldg(row + 1) : 0u;
        p2[s] = v2 ? __ldg(row + 2) : 0u;
    }

    for (int ib = 0; ib < PRE; ib += 8) {
#pragma unroll
        for (int s = 0; s < 8; s++) {
            int i = ib + s;
            int wi = i >> 5;
            int owner = wi / 3, sub = wi - owner * 3;
            unsigned myw = (sub == 0) ? r0 : ((sub == 1) ? r1 : r2);
            unsigned word = __shfl_sync(0xffffffffu, myw, owner);
            if (!((word >> (i & 31)) & 1u)) {
                if (lane == 0 && fin[i] && nk < POST) { kept[nk] = i; nk++; }
                r0 |= p0[s]; r1 |= p1[s]; r2 |= p2[s];
            }
            int ip = i + 8;
            if (ip < PRE) {
                const unsigned* row = M + (size_t)ip * NWORDS + b0;
                p0[s] = v0 ? __ldg(row) : 0u;
                p1[s] = v1 ? __ldg(row + 1) : 0u;
                p2[s] = v2 ? __ldg(row + 2) : 0u;
            }
        }
        int cnt = __shfl_sync(0xffffffffu, nk, 0);
        if (cnt >= POST) break;
    }
    if (lane == 0) s_nk = nk;
    __syncwarp();
    int NK = s_nk;

    for (int r = lane; r < POST; r += 32) {
        float4 b = make_float4(0.f, 0.f, 0.f, 0.f);
        float v = 0.f;
        if (r < NK) {
            b = *reinterpret_cast<const float4*>(&g_selbox[((size_t)img * PRE + kept[r]) * 4]);
            v = 1.f;
        }
        float* rp = out + OFF_ROI + ((size_t)img * POST + r) * 4;
        rp[0] = b.x; rp[1] = b.y; rp[2] = b.z; rp[3] = b.w;
        out[OFF_VAL + img * POST + r] = v;
    }
}

// ===================== launch =====================
extern "C" void kernel_launch(void* const* d_in, const int* in_sizes, int n_in,
                              void* d_out, int out_size)
{
    const float* x  = (const float*)d_in[0];
    const float* W1 = (const float*)d_in[1];
    const float* b1 = (const float*)d_in[2];
    const float* Ws = (const float*)d_in[3];
    const float* bs = (const float*)d_in[4];
    const float* Wl = (const float*)d_in[5];
    const float* bl = (const float*)d_in[6];
    const int* imh  = (const int*)d_in[7];
    const int* imw  = (const int*)d_in[8];
    float* out = (float*)d_out;

    cudaFuncSetAttribute(sort_local8k, cudaFuncAttributeMaxDynamicSharedMemorySize, 65536);
    cudaFuncSetAttribute(merge_local8k, cudaFuncAttributeMaxDynamicSharedMemorySize, 65536);
    cudaFuncSetAttribute(conv3x3_kernel, cudaFuncAttributeMaxDynamicSharedMemorySize, CONV_SMEM_B);

    // conv is the 4th launch (the one ncu profiles)
    anchors_kernel<<<(NANCH + 255) / 256, 256>>>(out + OFF_ANC);
    pad_keys_kernel<<<(N_IMG * (NS - NANCH) + 255) / 256, 256>>>();
    wtrans_kernel<<<(KTOT * C_IN + 255) / 256, 256>>>(W1);

    conv3x3_kernel<<<dim3(128, 4), 256, CONV_SMEM_B>>>(x, b1);
    heads_kernel<<<128, 128>>>(Ws, bs, Wl, bl, out);
    boxes_kernel<<<(N_IMG * NANCH + 255) / 256, 256>>>(out + OFF_LOC, imh, imw);

    sort_local8k<<<32, 512, 65536>>>();
    for (int k = 16384; k <= 65536; k <<= 1) {
        for (int j = k >> 1; j >= 8192; j >>= 1)
            sort_global<<<512, 256>>>(k, j);
        merge_local8k<<<32, 512, 65536>>>(k);
    }

    gather_kernel<<<(N_IMG * PRE + 255) / 256, 256>>>();
    iou_kernel<<<(N_IMG * PRE * NWORDS + 255) / 256, 256>>>();
    nms_kernel<<<4, 32>>>(out);
}

// round 14
// speedup vs baseline: 2.0368x; 1.0567x over previous
#include <cuda_runtime.h>
#include <math.h>
#include <stdint.h>

#define N_IMG 4
#define C_IN 512
#define SP 4096              // 64*64 per image
#define KTOT 4608            // 512*9
#define NANCH 36864          // 4096*9
#define NS 65536             // padded sort size per image
#define PRE 3000
#define POST 300
#define NWORDS 94            // ceil(3000/32)

// output layout (concatenated float32, reference return order)
#define OFF_LOC 0
#define OFF_SC  589824
#define OFF_ROI 884736
#define OFF_VAL 889536
#define OFF_ANC 890736

// -------- scratch (static device globals; no allocation) --------
__device__ float g_h[N_IMG * C_IN * SP];          // conv1 output, NCHW
__device__ float g_wt[KTOT * C_IN];               // W1 transposed, K reordered r*512+c
__device__ float g_fg[N_IMG * NANCH];             // softmax fg scores
__device__ float g_boxes[N_IMG * NANCH * 4];      // decoded+clipped boxes
__device__ unsigned long long g_keys[N_IMG * NS]; // sort keys
__device__ float g_selbox[N_IMG * PRE * 4];       // top-3000 boxes
__device__ int   g_selfin[N_IMG * PRE];           // finite-score flag
__device__ unsigned g_mask[N_IMG * PRE * NWORDS]; // iou>0.7 bitmask rows

__device__ __forceinline__ float read_scalar(const int* p) {
    int iv = *p;
    if (iv > 0 && iv < (1 << 24)) return (float)iv;
    return *reinterpret_cast<const float*>(p);
}

__device__ __forceinline__ uint32_t f2tf(float f) {
    uint32_t r;
    asm("cvt.rna.tf32.f32 %0, %1;" : "=r"(r) : "f"(f));
    return r;
}

// chained MMA: c += a*b
#define MMA_TF32(c, a, b) \
    asm("mma.sync.aligned.m16n8k8.row.col.f32.tf32.tf32.f32 " \
        "{%0,%1,%2,%3},{%4,%5,%6,%7},{%8,%9},{%0,%1,%2,%3};" \
        : "+f"((c)[0]), "+f"((c)[1]), "+f"((c)[2]), "+f"((c)[3]) \
        : "r"((a)[0]), "r"((a)[1]), "r"((a)[2]), "r"((a)[3]), \
          "r"((b)[0]), "r"((b)[1]))

// fresh MMA: c = a*b + 0   (d != c; kills accumulator bias chains)
#define MMA_TF32_Z(c, a, b) \
    asm("mma.sync.aligned.m16n8k8.row.col.f32.tf32.tf32.f32 " \
        "{%0,%1,%2,%3},{%4,%5,%6,%7},{%8,%9},{%10,%11,%12,%13};" \
        : "=f"((c)[0]), "=f"((c)[1]), "=f"((c)[2]), "=f"((c)[3]) \
        : "r"((a)[0]), "r"((a)[1]), "r"((a)[2]), "r"((a)[3]), \
          "r"((b)[0]), "r"((b)[1]), \
          "f"(0.f), "f"(0.f), "f"(0.f), "f"(0.f))

// ===================== pre-conv kernels (conv must be 4th launch for ncu) =====================
__global__ void anchors_kernel(float* __restrict__ anch_out)
{
    int li = blockIdx.x * blockDim.x + threadIdx.x;
    if (li >= NANCH) return;
    int pix = li / 9;
    int a = li - pix * 9;
    int y = pix >> 6, x = pix & 63;
    int ri = a / 3, si = a - ri * 3;
    float ratio = (ri == 0) ? 0.5f : ((ri == 1) ? 1.0f : 2.0f);
    float scl = (si == 0) ? 8.f : ((si == 1) ? 16.f : 32.f);
    float hs = (16.f * scl) * sqrtf(ratio);
    float ws = (16.f * scl) * sqrtf(1.0f / ratio);
    float sy = (float)(y * 16), sx = (float)(x * 16);
    float* ap = anch_out + (size_t)li * 4;
    ap[0] = sy + (8.f - hs * 0.5f);
    ap[1] = sx + (8.f - ws * 0.5f);
    ap[2] = sy + (8.f + hs * 0.5f);
    ap[3] = sx + (8.f + ws * 0.5f);
}

__global__ void pad_keys_kernel()
{
    int t = blockIdx.x * blockDim.x + threadIdx.x;
    int per = NS - NANCH;
    if (t >= N_IMG * per) return;
    int img = t / per, li = NANCH + (t - img * per);
    g_keys[(size_t)img * NS + li] = 0xFFFFFFFFFFFFFFFFull;
}

// W1[m][c*9+r]  ->  g_wt[(r*512+c)*512 + m]
__global__ void wtrans_kernel(const float* __restrict__ W1)
{
    int t = blockIdx.x * blockDim.x + threadIdx.x;
    if (t >= KTOT * C_IN) return;
    int k = t >> 9, m = t & 511;
    int rr = k >> 9, c = k & 511;
    g_wt[t] = W1[(size_t)m * KTOT + c * 9 + rr];
}

// ===================== conv 3x3 via mma.sync tf32 (3-pass hi/lo, segmented accum) ==============
// K reordered k = r*512 + c (tap-outer). CTA tile 128x128, 8 warps of 64x32; K chunk 16,
// double-buffered RAW-f32 smem tiles (hi/lo split happens in registers at consume time).
// Fill mapping is lane-fast (thread owns column n=tid&127, rows krow0+2i) -> coalesced LDG/STS.
#define TPAD 136
#define TILE_F (16 * TPAD)                 // 2176 floats per tile
#define BUF_F (2 * TILE_F)                 // A, B (raw f32)
#define CONV_SMEM_B (2 * BUF_F * 4)        // 34816 bytes
#define NCH 288

__global__ __launch_bounds__(256, 2) void conv3x3_kernel(
    const float* __restrict__ x, const float* __restrict__ bias)
{
    extern __shared__ float sm[];
    const int tid = threadIdx.x;
    const int n0 = blockIdx.x * 128;
    const int m0 = blockIdx.y * 128;
    const int wid = tid >> 5, lane = tid & 31;
    const int g = lane >> 2, tk = lane & 3;
    const int wm = wid >> 2, wn = wid & 3;

    // fill coordinates: this thread owns column n, k-rows krow0 + 2*i (i=0..7)
    const int n = tid & 127;
    const int krow0 = tid >> 7;           // 0 or 1
    const int img = n0 >> 12;
    const int col = n0 + n;
    const int ny = (col >> 6) & 63;
    const int nx = col & 63;
    const float* xim = x + (size_t)img * (C_IN * SP);

    float sum[4][4][4];
#pragma unroll
    for (int a = 0; a < 4; a++)
#pragma unroll
        for (int b = 0; b < 4; b++)
#pragma unroll
            for (int c = 0; c < 4; c++) sum[a][b][c] = 0.f;

    float av[8], bv[8];

#define LOADG(CH) do { \
    const int k0 = (CH) << 4; \
    const int rr = (CH) >> 5; \
    const int cb = k0 & 511; \
    const int ryy = rr / 3; \
    const int dy = ryy - 1, dx = rr - 3 * ryy - 1; \
    const int yy = ny + dy, xx = nx + dx; \
    const bool pred = ((unsigned)yy < 64u) && ((unsigned)xx < 64u); \
    const float* ap = g_wt + ((size_t)(k0 + krow0) << 9) + m0 + n; \
    const float* bp = xim + ((size_t)(cb + krow0) << 12) + (yy << 6) + xx; \
    _Pragma("unroll") \
    for (int i = 0; i < 8; i++) av[i] = ap[i * 1024]; \
    _Pragma("unroll") \
    for (int i = 0; i < 8; i++) bv[i] = pred ? bp[(size_t)i * 8192] : 0.f; \
    } while (0)

#define STORE_AB(BUF) do { \
    float* SA = sm + (BUF) * BUF_F + krow0 * TPAD + n; \
    float* SB = SA + TILE_F; \
    _Pragma("unroll") \
    for (int i = 0; i < 8; i++) { SA[i * 2 * TPAD] = av[i]; SB[i * 2 * TPAD] = bv[i]; } \
    } while (0)

    LOADG(0);
    STORE_AB(0);
    __syncthreads();

    int buf = 0;
    for (int ch = 0; ch < NCH; ch++) {
        const bool more = ch + 1 < NCH;
        if (more) LOADG(ch + 1);

        {
            const float* SA = sm + buf * BUF_F;
            const float* SB = SA + TILE_F;
            const int r0 = tk * TPAD;
            const int r4 = r0 + 4 * TPAD;
#pragma unroll
            for (int ks = 0; ks < 2; ks++) {
                const int ro = ks * 8 * TPAD;
                uint32_t bh[4][2], bl[4][2];
#pragma unroll
                for (int nf = 0; nf < 4; nf++) {
                    const int nb = wn * 32 + nf * 8 + g;
                    float b0 = SB[ro + r0 + nb];
                    float b1 = SB[ro + r4 + nb];
                    bh[nf][0] = f2tf(b0);
                    bl[nf][0] = f2tf(b0 - __uint_as_float(bh[nf][0]));
                    bh[nf][1] = f2tf(b1);
                    bl[nf][1] = f2tf(b1 - __uint_as_float(bh[nf][1]));
                }
#pragma unroll
                for (int mf = 0; mf < 4; mf++) {
                    const int mb = wm * 64 + mf * 16 + g;
                    float a0 = SA[ro + r0 + mb];
                    float a1 = SA[ro + r0 + mb + 8];
                    float a2 = SA[ro + r4 + mb];
                    float a3 = SA[ro + r4 + mb + 8];
                    uint32_t ah[4], al[4];
                    ah[0] = f2tf(a0); al[0] = f2tf(a0 - __uint_as_float(ah[0]));
                    ah[1] = f2tf(a1); al[1] = f2tf(a1 - __uint_as_float(ah[1]));
                    ah[2] = f2tf(a2); al[2] = f2tf(a2 - __uint_as_float(ah[2]));
                    ah[3] = f2tf(a3); al[3] = f2tf(a3 - __uint_as_float(ah[3]));
#pragma unroll
                    for (int nf = 0; nf < 4; nf++) {
                        float t[4];
                        MMA_TF32_Z(t, ah, bh[nf]);    // partial = Ahi*Bhi
                        MMA_TF32(t, ah, bl[nf]);      // + Ahi*Blo
                        MMA_TF32(t, al, bh[nf]);      // + Alo*Bhi
                        sum[mf][nf][0] += t[0];
                        sum[mf][nf][1] += t[1];
                        sum[mf][nf][2] += t[2];
                        sum[mf][nf][3] += t[3];
                    }
                }
            }
        }

        if (more) STORE_AB(buf ^ 1);
        __syncthreads();
        buf ^= 1;
    }

    // epilogue: bias + relu
    const int spb = n0 & 4095;
#pragma unroll
    for (int mf = 0; mf < 4; mf++) {
        const int m = m0 + wm * 64 + mf * 16 + g;
        const float bv0 = bias[m];
        const float bv1 = bias[m + 8];
        float* h0 = g_h + ((size_t)img * C_IN + m) * SP + spb;
        float* h1 = h0 + 8 * SP;
#pragma unroll
        for (int nf = 0; nf < 4; nf++) {
            const int nn = wn * 32 + nf * 8 + 2 * tk;
            float2 v0, v1;
            v0.x = fmaxf(sum[mf][nf][0] + bv0, 0.f);
            v0.y = fmaxf(sum[mf][nf][1] + bv0, 0.f);
            v1.x = fmaxf(sum[mf][nf][2] + bv1, 0.f);
            v1.y = fmaxf(sum[mf][nf][3] + bv1, 0.f);
            *reinterpret_cast<float2*>(h0 + nn) = v0;
            *reinterpret_cast<float2*>(h1 + nn) = v1;
        }
    }
}

// ===================== heads: 1x1 convs (18 score, 36 loc), transpose, softmax =====================
__global__ __launch_bounds__(128) void heads_kernel(
    const float* __restrict__ Ws, const float* __restrict__ bs,
    const float* __restrict__ Wl, const float* __restrict__ bl,
    float* __restrict__ out)
{
    __shared__ float Wt[54][64];
    const int tid = threadIdx.x;
    const int col = blockIdx.x * 128 + tid;
    const int img = col >> 12;
    const int sp = col & 4095;

    float acc[54];
#pragma unroll
    for (int o = 0; o < 54; o++) acc[o] = 0.f;

    for (int c0 = 0; c0 < C_IN; c0 += 64) {
        for (int i = tid; i < 54 * 64; i += 128) {
            int o = i >> 6, cc = i & 63;
            Wt[o][cc] = (o < 18) ? Ws[o * C_IN + c0 + cc] : Wl[(o - 18) * C_IN + c0 + cc];
        }
        __syncthreads();
        const float* hp = g_h + (size_t)img * C_IN * SP + (size_t)c0 * SP + sp;
#pragma unroll 4
        for (int cc = 0; cc < 64; cc++) {
            float xv = hp[(size_t)cc * SP];
#pragma unroll
            for (int o = 0; o < 54; o++) acc[o] += xv * Wt[o][cc];
        }
        __syncthreads();
    }

    const size_t base9 = (size_t)img * NANCH + (size_t)sp * 9;
#pragma unroll
    for (int o = 0; o < 18; o++) {
        float v = acc[o] + bs[o];
        out[OFF_SC + (base9 + (o >> 1)) * 2 + (o & 1)] = v;
    }
#pragma unroll
    for (int o = 0; o < 36; o++) {
        float v = acc[18 + o] + bl[o];
        out[OFF_LOC + (base9 + (o >> 2)) * 4 + (o & 3)] = v;
    }
#pragma unroll
    for (int a = 0; a < 9; a++) {
        float s0 = acc[2 * a] + bs[2 * a];
        float s1 = acc[2 * a + 1] + bs[2 * a + 1];
        float m = fmaxf(s0, s1);
        float e0 = expf(s0 - m), e1 = expf(s1 - m);
        g_fg[base9 + a] = e1 / (e0 + e1);
    }
}

// ===================== loc2bbox + clip + min-size + sort keys =====================
__global__ void boxes_kernel(const float* __restrict__ locs,
                             const int* __restrict__ imh_p, const int* __restrict__ imw_p)
{
    int t = blockIdx.x * blockDim.x + threadIdx.x;
    if (t >= N_IMG * NANCH) return;
    int img = t / NANCH;
    int li = t - img * NANCH;

    int pix = li / 9;
    int a = li - pix * 9;
    int y = pix >> 6, x = pix & 63;
    int ri = a / 3, si = a - ri * 3;
    float ratio = (ri == 0) ? 0.5f : ((ri == 1) ? 1.0f : 2.0f);
    float scl = (si == 0) ? 8.f : ((si == 1) ? 16.f : 32.f);
    float hs = (16.f * scl) * sqrtf(ratio);
    float ws = (16.f * scl) * sqrtf(1.0f / ratio);
    float sy = (float)(y * 16), sx = (float)(x * 16);
    float ay1 = sy + (8.f - hs * 0.5f);
    float ax1 = sx + (8.f - ws * 0.5f);
    float ay2 = sy + (8.f + hs * 0.5f);
    float ax2 = sx + (8.f + ws * 0.5f);

    const float* lp = locs + ((size_t)img * NANCH + li) * 4;
    float dy = lp[0], dx = lp[1], dh = lp[2], dw = lp[3];
    float ah = ay2 - ay1, aw = ax2 - ax1;
    float acy = ay1 + 0.5f * ah, acx = ax1 + 0.5f * aw;
    float cy = dy * ah + acy, cx = dx * aw + acx;
    float hb = expf(dh) * ah, wb = expf(dw) * aw;

    float imh = read_scalar(imh_p);
    float imw = read_scalar(imw_p);
    float y1 = fminf(fmaxf(cy - 0.5f * hb, 0.f), imh);
    float x1 = fminf(fmaxf(cx - 0.5f * wb, 0.f), imw);
    float y2 = fminf(fmaxf(cy + 0.5f * hb, 0.f), imh);
    float x2 = fminf(fmaxf(cx + 0.5f * wb, 0.f), imw);

    float* bp = g_boxes + ((size_t)img * NANCH + li) * 4;
    bp[0] = y1; bp[1] = x1; bp[2] = y2; bp[3] = x2;

    bool valid = ((y2 - y1) >= 16.f) && ((x2 - x1) >= 16.f);
    float s = valid ? g_fg[(size_t)img * NANCH + li] : -INFINITY;
    unsigned u = __float_as_uint(s);
    unsigned desc = (u & 0x80000000u) ? u : (~u & 0x7FFFFFFFu);   // ascending key = descending score
    g_keys[(size_t)img * NS + li] = ((unsigned long long)desc << 32) | (unsigned)li;
}

// ===================== bitonic sort (per-image 65536 keys, ascending) =====================
__global__ __launch_bounds__(512) void sort_local8k()
{
    extern __shared__ unsigned long long s[];
    const int base = blockIdx.x * 8192;
    for (int i = threadIdx.x; i < 8192; i += 512) s[i] = g_keys[base + i];
    __syncthreads();
    for (int k = 2; k <= 8192; k <<= 1) {
        for (int j = k >> 1; j > 0; j >>= 1) {
            for (int t = threadIdx.x; t < 4096; t += 512) {
                int i = ((t & ~(j - 1)) << 1) | (t & (j - 1));
                int l = i | j;
                bool up = (((base + i) & k) == 0);
                unsigned long long va = s[i], vb = s[l];
                if ((va > vb) == up) { s[i] = vb; s[l] = va; }
            }
            __syncthreads();
        }
    }
    for (int i = threadIdx.x; i < 8192; i += 512) g_keys[base + i] = s[i];
}

__global__ void sort_global(int k, int j)
{
    int t = blockIdx.x * blockDim.x + threadIdx.x;  // 4*32768
    int img = t >> 15, tt = t & 32767;
    int i = ((tt & ~(j - 1)) << 1) | (tt & (j - 1));
    int l = i | j;
    unsigned long long* p = g_keys + (size_t)img * NS;
    bool up = ((i & k) == 0);
    unsigned long long va = p[i], vb = p[l];
    if ((va > vb) == up) { p[i] = vb; p[l] = va; }
}

__global__ __launch_bounds__(512) void merge_local8k(int k)
{
    extern __shared__ unsigned long long s[];
    const int base = blockIdx.x * 8192;
    for (int i = threadIdx.x; i < 8192; i += 512) s[i] = g_keys[base + i];
    __syncthreads();
    bool up = (((base & (NS - 1)) & k) == 0);
    for (int j = 4096; j > 0; j >>= 1) {
        for (int t = threadIdx.x; t < 4096; t += 512) {
            int i = ((t & ~(j - 1)) << 1) | (t & (j - 1));
            int l = i | j;
            unsigned long long va = s[i], vb = s[l];
            if ((va > vb) == up) { s[i] = vb; s[l] = va; }
        }
        __syncthreads();
    }
    for (int i = threadIdx.x; i < 8192; i += 512) g_keys[base + i] = s[i];
}

// ===================== gather top-3000 =====================
__global__ void gather_kernel()
{
    int t = blockIdx.x * blockDim.x + threadIdx.x;
    if (t >= N_IMG * PRE) return;
    int img = t / PRE, r = t - img * PRE;
    unsigned long long key = g_keys[(size_t)img * NS + r];
    int li = (int)(key & 0xFFFFFFFFull);
    unsigned desc = (unsigned)(key >> 32);
    g_selfin[img * PRE + r] = (desc < 0xFF800000u) ? 1 : 0;  // finite score
    float4 b = *reinterpret_cast<const float4*>(&g_boxes[((size_t)img * NANCH + li) * 4]);
    *reinterpret_cast<float4*>(&g_selbox[((size_t)img * PRE + r) * 4]) = b;
}

// ===================== IoU > 0.7 bitmask =====================
__global__ void iou_kernel()
{
    int t = blockIdx.x * blockDim.x + threadIdx.x;
    if (t >= N_IMG * PRE * NWORDS) return;
    int img = t / (PRE * NWORDS);
    int rem = t - img * (PRE * NWORDS);
    int i = rem / NWORDS;
    int w = rem - i * NWORDS;
    const float* B = g_selbox + (size_t)img * PRE * 4;
    float4 bi = *reinterpret_cast<const float4*>(B + (size_t)i * 4);
    float ai = (bi.z - bi.x) * (bi.w - bi.y);
    unsigned bits = 0;
    int j0 = w * 32;
#pragma unroll 4
    for (int jj = 0; jj < 32; jj++) {
        int j = j0 + jj;
        if (j >= PRE) break;
        float4 bj = *reinterpret_cast<const float4*>(B + (size_t)j * 4);
        float yy1 = fmaxf(bi.x, bj.x), xx1 = fmaxf(bi.y, bj.y);
        float yy2 = fminf(bi.z, bj.z), xx2 = fminf(bi.w, bj.w);
        float ih = fmaxf(yy2 - yy1, 0.f), iw = fmaxf(xx2 - xx1, 0.f);
        float inter = ih * iw;
        float aj = (bj.z - bj.x) * (bj.w - bj.y);
        float uni = ai + aj - inter;
        float iou = (uni > 0.f) ? (inter / uni) : 0.f;
        if (iou > 0.7f) bits |= (1u << jj);
    }
    g_mask[((size_t)img * PRE + i) * NWORDS + w] = bits;
}

// ===================== sequential greedy NMS with 8-deep row prefetch =====================
__global__ void nms_kernel(float* __restrict__ out)
{
    const int img = blockIdx.x;
    const int lane = threadIdx.x;
    __shared__ int kept[POST];
    __shared__ int s_nk;
    unsigned r0 = 0, r1 = 0, r2 = 0;   // lane owns removed-words [3*lane .. 3*lane+2]
    int nk = 0;
    const unsigned* M = g_mask + (size_t)img * PRE * NWORDS;
    const int* fin = g_selfin + img * PRE;
    const int b0 = lane * 3;
    const bool v0 = (b0 < NWORDS), v1 = (b0 + 1 < NWORDS), v2 = (b0 + 2 < NWORDS);

    unsigned p0[8], p1[8], p2[8];      // prefetched rows i..i+7
#pragma unroll
    for (int s = 0; s < 8; s++) {
        const unsigned* row = M + (size_t)s * NWORDS + b0;
        p0[s] = v0 ? __ldg(row) : 0u;
        p1[s] = v1 ? __ldg(row + 1) : 0u;
        p2[s] = v2 ? __ldg(row + 2) : 0u;
    }

    for (int ib = 0; ib < PRE; ib += 8) {
#pragma unroll
        for (int s = 0; s < 8; s++) {
            int i = ib + s;
            int wi = i >> 5;
            int owner = wi / 3, sub = wi - owner * 3;
            unsigned myw = (sub == 0) ? r0 : ((sub == 1) ? r1 : r2);
            unsigned word = __shfl_sync(0xffffffffu, myw, owner);
            if (!((word >> (i & 31)) & 1u)) {
                if (lane == 0 && fin[i] && nk < POST) { kept[nk] = i; nk++; }
                r0 |= p0[s]; r1 |= p1[s]; r2 |= p2[s];
            }
            int ip = i + 8;
            if (ip < PRE) {
                const unsigned* row = M + (size_t)ip * NWORDS + b0;
                p0[s] = v0 ? __ldg(row) : 0u;
                p1[s] = v1 ? __ldg(row + 1) : 0u;
                p2[s] = v2 ? __ldg(row + 2) : 0u;
            }
        }
        int cnt = __shfl_sync(0xffffffffu, nk, 0);
        if (cnt >= POST) break;
    }
    if (lane == 0) s_nk = nk;
    __syncwarp();
    int NK = s_nk;

    for (int r = lane; r < POST; r += 32) {
        float4 b = make_float4(0.f, 0.f, 0.f, 0.f);
        float v = 0.f;
        if (r < NK) {
            b = *reinterpret_cast<const float4*>(&g_selbox[((size_t)img * PRE + kept[r]) * 4]);
            v = 1.f;
        }
        float* rp = out + OFF_ROI + ((size_t)img * POST + r) * 4;
        rp[0] = b.x; rp[1] = b.y; rp[2] = b.z; rp[3] = b.w;
        out[OFF_VAL + img * POST + r] = v;
    }
}

// ===================== launch =====================
extern "C" void kernel_launch(void* const* d_in, const int* in_sizes, int n_in,
                              void* d_out, int out_size)
{
    const float* x  = (const float*)d_in[0];
    const float* W1 = (const float*)d_in[1];
    const float* b1 = (const float*)d_in[2];
    const float* Ws = (const float*)d_in[3];
    const float* bs = (const float*)d_in[4];
    const float* Wl = (const float*)d_in[5];
    const float* bl = (const float*)d_in[6];
    const int* imh  = (const int*)d_in[7];
    const int* imw  = (const int*)d_in[8];
    float* out = (float*)d_out;

    cudaFuncSetAttribute(sort_local8k, cudaFuncAttributeMaxDynamicSharedMemorySize, 65536);
    cudaFuncSetAttribute(merge_local8k, cudaFuncAttributeMaxDynamicSharedMemorySize, 65536);
    cudaFuncSetAttribute(conv3x3_kernel, cudaFuncAttributeMaxDynamicSharedMemorySize, CONV_SMEM_B);

    // conv is the 4th launch (the one ncu profiles)
    anchors_kernel<<<(NANCH + 255) / 256, 256>>>(out + OFF_ANC);
    pad_keys_kernel<<<(N_IMG * (NS - NANCH) + 255) / 256, 256>>>();
    wtrans_kernel<<<(KTOT * C_IN + 255) / 256, 256>>>(W1);

    conv3x3_kernel<<<dim3(128, 4), 256, CONV_SMEM_B>>>(x, b1);
    heads_kernel<<<128, 128>>>(Ws, bs, Wl, bl, out);
    boxes_kernel<<<(N_IMG * NANCH + 255) / 256, 256>>>(out + OFF_LOC, imh, imw);

    sort_local8k<<<32, 512, 65536>>>();
    for (int k = 16384; k <= 65536; k <<= 1) {
        for (int j = k >> 1; j >= 8192; j >>= 1)
            sort_global<<<512, 256>>>(k, j);
        merge_local8k<<<32, 512, 65536>>>(k);
    }

    gather_kernel<<<(N_IMG * PRE + 255) / 256, 256>>>();
    iou_kernel<<<(N_IMG * PRE * NWORDS + 255) / 256, 256>>>();
    nms_kernel<<<4, 32>>>(out);
}

// round 16
// speedup vs baseline: 2.1426x; 1.0520x over previous
#include <cuda_runtime.h>
#include <math.h>
#include <stdint.h>

#define N_IMG 4
#define C_IN 512
#define SP 4096              // 64*64 per image
#define KTOT 4608            // 512*9
#define NANCH 36864          // 4096*9
#define NS 65536             // padded sort size per image
#define PRE 3000
#define POST 300
#define NWORDS 94            // ceil(3000/32)

// output layout (concatenated float32, reference return order)
#define OFF_LOC 0
#define OFF_SC  589824
#define OFF_ROI 884736
#define OFF_VAL 889536
#define OFF_ANC 890736

// -------- scratch (static device globals; no allocation) --------
__device__ float g_h[N_IMG * C_IN * SP];          // conv1 output, NCHW
__device__ uint32_t g_wt_hi[KTOT * C_IN];         // W1 transposed hi (tf32 bits), k = r*512+c
__device__ uint32_t g_wt_lo[KTOT * C_IN];         // W1 transposed lo residual (tf32 bits)
__device__ float g_fg[N_IMG * NANCH];             // softmax fg scores
__device__ float g_boxes[N_IMG * NANCH * 4];      // decoded+clipped boxes
__device__ unsigned long long g_keys[N_IMG * NS]; // sort keys
__device__ float g_selbox[N_IMG * PRE * 4];       // top-3000 boxes
__device__ int   g_selfin[N_IMG * PRE];           // finite-score flag
__device__ unsigned g_mask[N_IMG * PRE * NWORDS]; // iou>0.7 bitmask rows

__device__ __forceinline__ float read_scalar(const int* p) {
    int iv = *p;
    if (iv > 0 && iv < (1 << 24)) return (float)iv;
    return *reinterpret_cast<const float*>(p);
}

__device__ __forceinline__ uint32_t f2tf(float f) {
    uint32_t r;
    asm("cvt.rna.tf32.f32 %0, %1;" : "=r"(r) : "f"(f));
    return r;
}

// chained MMA: c += a*b
#define MMA_TF32(c, a, b) \
    asm("mma.sync.aligned.m16n8k8.row.col.f32.tf32.tf32.f32 " \
        "{%0,%1,%2,%3},{%4,%5,%6,%7},{%8,%9},{%0,%1,%2,%3};" \
        : "+f"((c)[0]), "+f"((c)[1]), "+f"((c)[2]), "+f"((c)[3]) \
        : "r"((a)[0]), "r"((a)[1]), "r"((a)[2]), "r"((a)[3]), \
          "r"((b)[0]), "r"((b)[1]))

// fresh MMA: c = a*b + 0   (d != c; kills accumulator bias chains)
#define MMA_TF32_Z(c, a, b) \
    asm("mma.sync.aligned.m16n8k8.row.col.f32.tf32.tf32.f32 " \
        "{%0,%1,%2,%3},{%4,%5,%6,%7},{%8,%9},{%10,%11,%12,%13};" \
        : "=f"((c)[0]), "=f"((c)[1]), "=f"((c)[2]), "=f"((c)[3]) \
        : "r"((a)[0]), "r"((a)[1]), "r"((a)[2]), "r"((a)[3]), \
          "r"((b)[0]), "r"((b)[1]), \
          "f"(0.f), "f"(0.f), "f"(0.f), "f"(0.f))

// ===================== pre-conv kernels (conv must be 4th launch for ncu) =====================
__global__ void anchors_kernel(float* __restrict__ anch_out)
{
    int li = blockIdx.x * blockDim.x + threadIdx.x;
    if (li >= NANCH) return;
    int pix = li / 9;
    int a = li - pix * 9;
    int y = pix >> 6, x = pix & 63;
    int ri = a / 3, si = a - ri * 3;
    float ratio = (ri == 0) ? 0.5f : ((ri == 1) ? 1.0f : 2.0f);
    float scl = (si == 0) ? 8.f : ((si == 1) ? 16.f : 32.f);
    float hs = (16.f * scl) * sqrtf(ratio);
    float ws = (16.f * scl) * sqrtf(1.0f / ratio);
    float sy = (float)(y * 16), sx = (float)(x * 16);
    float* ap = anch_out + (size_t)li * 4;
    ap[0] = sy + (8.f - hs * 0.5f);
    ap[1] = sx + (8.f - ws * 0.5f);
    ap[2] = sy + (8.f + hs * 0.5f);
    ap[3] = sx + (8.f + ws * 0.5f);
}

__global__ void pad_keys_kernel()
{
    int t = blockIdx.x * blockDim.x + threadIdx.x;
    int per = NS - NANCH;
    if (t >= N_IMG * per) return;
    int img = t / per, li = NANCH + (t - img * per);
    g_keys[(size_t)img * NS + li] = 0xFFFFFFFFFFFFFFFFull;
}

// W1[m][c*9+r]  ->  hi/lo tf32 planes at [(r*512+c)*512 + m]
__global__ void wtrans_kernel(const float* __restrict__ W1)
{
    int t = blockIdx.x * blockDim.x + threadIdx.x;
    if (t >= KTOT * C_IN) return;
    int k = t >> 9, m = t & 511;
    int rr = k >> 9, c = k & 511;
    float w = W1[(size_t)m * KTOT + c * 9 + rr];
    uint32_t h = f2tf(w);
    g_wt_hi[t] = h;
    g_wt_lo[t] = f2tf(w - __uint_as_float(h));
}

// ===================== conv 3x3 via mma.sync tf32 (3-pass hi/lo, segmented accum) ==============
// K reordered k = r*512 + c (tap-outer). CTA tile 128x128, 8 warps of 64x32; K chunk 16,
// double-buffered smem: 4 tf32 tiles (Ahi, Alo, Bhi, Blo). ALL hi/lo conversion happens
// outside the consume loop: A preprocessed in wtrans; B split once at fill time.
// Fill mapping lane-fast (thread owns column n=tid&127, rows krow0+2i) -> coalesced LDG/STS.
#define TPAD 136
#define TILE_F (16 * TPAD)                 // 2176 words per tile
#define BUF_F (4 * TILE_F)                 // Ahi, Alo, Bhi, Blo
#define CONV_SMEM_B (2 * BUF_F * 4)        // 69632 bytes
#define NCH 288

__global__ __launch_bounds__(256, 2) void conv3x3_kernel(
    const float* __restrict__ x, const float* __restrict__ bias)
{
    extern __shared__ uint32_t smu[];
    const int tid = threadIdx.x;
    const int n0 = blockIdx.x * 128;
    const int m0 = blockIdx.y * 128;
    const int wid = tid >> 5, lane = tid & 31;
    const int g = lane >> 2, tk = lane & 3;
    const int wm = wid >> 2, wn = wid & 3;

    // fill coordinates: this thread owns column n, k-rows krow0 + 2*i (i=0..7)
    const int n = tid & 127;
    const int krow0 = tid >> 7;           // 0 or 1
    const int img = n0 >> 12;
    const int col = n0 + n;
    const int ny = (col >> 6) & 63;
    const int nx = col & 63;
    const float* xim = x + (size_t)img * (C_IN * SP);

    float sum[4][4][4];
#pragma unroll
    for (int a = 0; a < 4; a++)
#pragma unroll
        for (int b = 0; b < 4; b++)
#pragma unroll
            for (int c = 0; c < 4; c++) sum[a][b][c] = 0.f;

    uint32_t avh[8], avl[8];
    float bv[8];

#define LOADG(CH) do { \
    const int k0 = (CH) << 4; \
    const int rr = (CH) >> 5; \
    const int cb = k0 & 511; \
    const int ryy = rr / 3; \
    const int dy = ryy - 1, dx = rr - 3 * ryy - 1; \
    const int yy = ny + dy, xx = nx + dx; \
    const bool pred = ((unsigned)yy < 64u) && ((unsigned)xx < 64u); \
    const size_t aoff = ((size_t)(k0 + krow0) << 9) + m0 + n; \
    const uint32_t* aph = g_wt_hi + aoff; \
    const uint32_t* apl = g_wt_lo + aoff; \
    const float* bp = xim + ((size_t)(cb + krow0) << 12) + (yy << 6) + xx; \
    _Pragma("unroll") \
    for (int i = 0; i < 8; i++) { avh[i] = aph[i * 1024]; avl[i] = apl[i * 1024]; } \
    _Pragma("unroll") \
    for (int i = 0; i < 8; i++) bv[i] = pred ? bp[(size_t)i * 8192] : 0.f; \
    } while (0)

#define STORE_AB(BUF) do { \
    uint32_t* SAh = smu + (BUF) * BUF_F + krow0 * TPAD + n; \
    uint32_t* SAl = SAh + TILE_F; \
    uint32_t* SBh = SAh + 2 * TILE_F; \
    uint32_t* SBl = SAh + 3 * TILE_F; \
    _Pragma("unroll") \
    for (int i = 0; i < 8; i++) { \
        SAh[i * 2 * TPAD] = avh[i]; \
        SAl[i * 2 * TPAD] = avl[i]; \
        uint32_t h = f2tf(bv[i]); \
        SBh[i * 2 * TPAD] = h; \
        SBl[i * 2 * TPAD] = f2tf(bv[i] - __uint_as_float(h)); \
    } } while (0)

    LOADG(0);
    STORE_AB(0);
    __syncthreads();

    int buf = 0;
    for (int ch = 0; ch < NCH; ch++) {
        const bool more = ch + 1 < NCH;
        if (more) LOADG(ch + 1);

        {
            const uint32_t* SAh = smu + buf * BUF_F;
            const uint32_t* SAl = SAh + TILE_F;
            const uint32_t* SBh = SAh + 2 * TILE_F;
            const uint32_t* SBl = SAh + 3 * TILE_F;
            const int r0 = tk * TPAD;
            const int r4 = r0 + 4 * TPAD;
#pragma unroll
            for (int ks = 0; ks < 2; ks++) {
                const int ro = ks * 8 * TPAD;
                uint32_t bh[4][2], bl[4][2];
#pragma unroll
                for (int nf = 0; nf < 4; nf++) {
                    const int nb = wn * 32 + nf * 8 + g;
                    bh[nf][0] = SBh[ro + r0 + nb];
                    bh[nf][1] = SBh[ro + r4 + nb];
                    bl[nf][0] = SBl[ro + r0 + nb];
                    bl[nf][1] = SBl[ro + r4 + nb];
                }
#pragma unroll
                for (int mf = 0; mf < 4; mf++) {
                    const int mb = wm * 64 + mf * 16 + g;
                    uint32_t ah[4], al[4];
                    ah[0] = SAh[ro + r0 + mb];   ah[1] = SAh[ro + r0 + mb + 8];
                    ah[2] = SAh[ro + r4 + mb];   ah[3] = SAh[ro + r4 + mb + 8];
                    al[0] = SAl[ro + r0 + mb];   al[1] = SAl[ro + r0 + mb + 8];
                    al[2] = SAl[ro + r4 + mb];   al[3] = SAl[ro + r4 + mb + 8];
#pragma unroll
                    for (int nf = 0; nf < 4; nf++) {
                        float t[4];
                        MMA_TF32_Z(t, ah, bh[nf]);    // partial = Ahi*Bhi
                        MMA_TF32(t, ah, bl[nf]);      // + Ahi*Blo
                        MMA_TF32(t, al, bh[nf]);      // + Alo*Bhi
                        sum[mf][nf][0] += t[0];
                        sum[mf][nf][1] += t[1];
                        sum[mf][nf][2] += t[2];
                        sum[mf][nf][3] += t[3];
                    }
                }
            }
        }

        if (more) STORE_AB(buf ^ 1);
        __syncthreads();
        buf ^= 1;
    }

    // epilogue: bias + relu
    const int spb = n0 & 4095;
#pragma unroll
    for (int mf = 0; mf < 4; mf++) {
        const int m = m0 + wm * 64 + mf * 16 + g;
        const float bv0 = bias[m];
        const float bv1 = bias[m + 8];
        float* h0 = g_h + ((size_t)img * C_IN + m) * SP + spb;
        float* h1 = h0 + 8 * SP;
#pragma unroll
        for (int nf = 0; nf < 4; nf++) {
            const int nn = wn * 32 + nf * 8 + 2 * tk;
            float2 v0, v1;
            v0.x = fmaxf(sum[mf][nf][0] + bv0, 0.f);
            v0.y = fmaxf(sum[mf][nf][1] + bv0, 0.f);
            v1.x = fmaxf(sum[mf][nf][2] + bv1, 0.f);
            v1.y = fmaxf(sum[mf][nf][3] + bv1, 0.f);
            *reinterpret_cast<float2*>(h0 + nn) = v0;
            *reinterpret_cast<float2*>(h1 + nn) = v1;
        }
    }
}

// ===================== heads: 1x1 convs (18 score, 36 loc), transpose, softmax =====================
__global__ __launch_bounds__(128) void heads_kernel(
    const float* __restrict__ Ws, const float* __restrict__ bs,
    const float* __restrict__ Wl, const float* __restrict__ bl,
    float* __restrict__ out)
{
    __shared__ float Wt[54][64];
    const int tid = threadIdx.x;
    const int col = blockIdx.x * 128 + tid;
    const int img = col >> 12;
    const int sp = col & 4095;

    float acc[54];
#pragma unroll
    for (int o = 0; o < 54; o++) acc[o] = 0.f;

    for (int c0 = 0; c0 < C_IN; c0 += 64) {
        for (int i = tid; i < 54 * 64; i += 128) {
            int o = i >> 6, cc = i & 63;
            Wt[o][cc] = (o < 18) ? Ws[o * C_IN + c0 + cc] : Wl[(o - 18) * C_IN + c0 + cc];
        }
        __syncthreads();
        const float* hp = g_h + (size_t)img * C_IN * SP + (size_t)c0 * SP + sp;
#pragma unroll 4
        for (int cc = 0; cc < 64; cc++) {
            float xv = hp[(size_t)cc * SP];
#pragma unroll
            for (int o = 0; o < 54; o++) acc[o] += xv * Wt[o][cc];
        }
        __syncthreads();
    }

    const size_t base9 = (size_t)img * NANCH + (size_t)sp * 9;
#pragma unroll
    for (int o = 0; o < 18; o++) {
        float v = acc[o] + bs[o];
        out[OFF_SC + (base9 + (o >> 1)) * 2 + (o & 1)] = v;
    }
#pragma unroll
    for (int o = 0; o < 36; o++) {
        float v = acc[18 + o] + bl[o];
        out[OFF_LOC + (base9 + (o >> 2)) * 4 + (o & 3)] = v;
    }
#pragma unroll
    for (int a = 0; a < 9; a++) {
        float s0 = acc[2 * a] + bs[2 * a];
        float s1 = acc[2 * a + 1] + bs[2 * a + 1];
        float m = fmaxf(s0, s1);
        float e0 = expf(s0 - m), e1 = expf(s1 - m);
        g_fg[base9 + a] = e1 / (e0 + e1);
    }
}

// ===================== loc2bbox + clip + min-size + sort keys =====================
__global__ void boxes_kernel(const float* __restrict__ locs,
                             const int* __restrict__ imh_p, const int* __restrict__ imw_p)
{
    int t = blockIdx.x * blockDim.x + threadIdx.x;
    if (t >= N_IMG * NANCH) return;
    int img = t / NANCH;
    int li = t - img * NANCH;

    int pix = li / 9;
    int a = li - pix * 9;
    int y = pix >> 6, x = pix & 63;
    int ri = a / 3, si = a - ri * 3;
    float ratio = (ri == 0) ? 0.5f : ((ri == 1) ? 1.0f : 2.0f);
    float scl = (si == 0) ? 8.f : ((si == 1) ? 16.f : 32.f);
    float hs = (16.f * scl) * sqrtf(ratio);
    float ws = (16.f * scl) * sqrtf(1.0f / ratio);
    float sy = (float)(y * 16), sx = (float)(x * 16);
    float ay1 = sy + (8.f - hs * 0.5f);
    float ax1 = sx + (8.f - ws * 0.5f);
    float ay2 = sy + (8.f + hs * 0.5f);
    float ax2 = sx + (8.f + ws * 0.5f);

    const float* lp = locs + ((size_t)img * NANCH + li) * 4;
    float dy = lp[0], dx = lp[1], dh = lp[2], dw = lp[3];
    float ah = ay2 - ay1, aw = ax2 - ax1;
    float acy = ay1 + 0.5f * ah, acx = ax1 + 0.5f * aw;
    float cy = dy * ah + acy, cx = dx * aw + acx;
    float hb = expf(dh) * ah, wb = expf(dw) * aw;

    float imh = read_scalar(imh_p);
    float imw = read_scalar(imw_p);
    float y1 = fminf(fmaxf(cy - 0.5f * hb, 0.f), imh);
    float x1 = fminf(fmaxf(cx - 0.5f * wb, 0.f), imw);
    float y2 = fminf(fmaxf(cy + 0.5f * hb, 0.f), imh);
    float x2 = fminf(fmaxf(cx + 0.5f * wb, 0.f), imw);

    float* bp = g_boxes + ((size_t)img * NANCH + li) * 4;
    bp[0] = y1; bp[1] = x1; bp[2] = y2; bp[3] = x2;

    bool valid = ((y2 - y1) >= 16.f) && ((x2 - x1) >= 16.f);
    float s = valid ? g_fg[(size_t)img * NANCH + li] : -INFINITY;
    unsigned u = __float_as_uint(s);
    unsigned desc = (u & 0x80000000u) ? u : (~u & 0x7FFFFFFFu);   // ascending key = descending score
    g_keys[(size_t)img * NS + li] = ((unsigned long long)desc << 32) | (unsigned)li;
}

// ===================== bitonic sort (per-image 65536 keys, ascending) =====================
__global__ __launch_bounds__(512) void sort_local8k()
{
    extern __shared__ unsigned long long s[];
    const int base = blockIdx.x * 8192;
    for (int i = threadIdx.x; i < 8192; i += 512) s[i] = g_keys[base + i];
    __syncthreads();
    for (int k = 2; k <= 8192; k <<= 1) {
        for (int j = k >> 1; j > 0; j >>= 1) {
            for (int t = threadIdx.x; t < 4096; t += 512) {
                int i = ((t & ~(j - 1)) << 1) | (t & (j - 1));
                int l = i | j;
                bool up = (((base + i) & k) == 0);
                unsigned long long va = s[i], vb = s[l];
                if ((va > vb) == up) { s[i] = vb; s[l] = va; }
            }
            __syncthreads();
        }
    }
    for (int i = threadIdx.x; i < 8192; i += 512) g_keys[base + i] = s[i];
}

__global__ void sort_global(int k, int j)
{
    int t = blockIdx.x * blockDim.x + threadIdx.x;  // 4*32768
    int img = t >> 15, tt = t & 32767;
    int i = ((tt & ~(j - 1)) << 1) | (tt & (j - 1));
    int l = i | j;
    unsigned long long* p = g_keys + (size_t)img * NS;
    bool up = ((i & k) == 0);
    unsigned long long va = p[i], vb = p[l];
    if ((va > vb) == up) { p[i] = vb; p[l] = va; }
}

__global__ __launch_bounds__(512) void merge_local8k(int k)
{
    extern __shared__ unsigned long long s[];
    const int base = blockIdx.x * 8192;
    for (int i = threadIdx.x; i < 8192; i += 512) s[i] = g_keys[base + i];
    __syncthreads();
    bool up = (((base & (NS - 1)) & k) == 0);
    for (int j = 4096; j > 0; j >>= 1) {
        for (int t = threadIdx.x; t < 4096; t += 512) {
            int i = ((t & ~(j - 1)) << 1) | (t & (j - 1));
            int l = i | j;
            unsigned long long va = s[i], vb = s[l];
            if ((va > vb) == up) { s[i] = vb; s[l] = va; }
        }
        __syncthreads();
    }
    for (int i = threadIdx.x; i < 8192; i += 512) g_keys[base + i] = s[i];
}

// ===================== gather top-3000 =====================
__global__ void gather_kernel()
{
    int t = blockIdx.x * blockDim.x + threadIdx.x;
    if (t >= N_IMG * PRE) return;
    int img = t / PRE, r = t - img * PRE;
    unsigned long long key = g_keys[(size_t)img * NS + r];
    int li = (int)(key & 0xFFFFFFFFull);
    unsigned desc = (unsigned)(key >> 32);
    g_selfin[img * PRE + r] = (desc < 0xFF800000u) ? 1 : 0;  // finite score
    float4 b = *reinterpret_cast<const float4*>(&g_boxes[((size_t)img * NANCH + li) * 4]);
    *reinterpret_cast<float4*>(&g_selbox[((size_t)img * PRE + r) * 4]) = b;
}

// ===================== IoU > 0.7 bitmask =====================
__global__ void iou_kernel()
{
    int t = blockIdx.x * blockDim.x + threadIdx.x;
    if (t >= N_IMG * PRE * NWORDS) return;
    int img = t / (PRE * NWORDS);
    int rem = t - img * (PRE * NWORDS);
    int i = rem / NWORDS;
    int w = rem - i * NWORDS;
    const float* B = g_selbox + (size_t)img * PRE * 4;
    float4 bi = *reinterpret_cast<const float4*>(B + (size_t)i * 4);
    float ai = (bi.z - bi.x) * (bi.w - bi.y);
    unsigned bits = 0;
    int j0 = w * 32;
#pragma unroll 4
    for (int jj = 0; jj < 32; jj++) {
        int j = j0 + jj;
        if (j >= PRE) break;
        float4 bj = *reinterpret_cast<const float4*>(B + (size_t)j * 4);
        float yy1 = fmaxf(bi.x, bj.x), xx1 = fmaxf(bi.y, bj.y);
        float yy2 = fminf(bi.z, bj.z), xx2 = fminf(bi.w, bj.w);
        float ih = fmaxf(yy2 - yy1, 0.f), iw = fmaxf(xx2 - xx1, 0.f);
        float inter = ih * iw;
        float aj = (bj.z - bj.x) * (bj.w - bj.y);
        float uni = ai + aj - inter;
        float iou = (uni > 0.f) ? (inter / uni) : 0.f;
        if (iou > 0.7f) bits |= (1u << jj);
    }
    g_mask[((size_t)img * PRE + i) * NWORDS + w] = bits;
}

// ===================== sequential greedy NMS with 8-deep row prefetch =====================
__global__ void nms_kernel(float* __restrict__ out)
{
    const int img = blockIdx.x;
    const int lane = threadIdx.x;
    __shared__ int kept[POST];
    __shared__ int s_nk;
    unsigned r0 = 0, r1 = 0, r2 = 0;   // lane owns removed-words [3*lane .. 3*lane+2]
    int nk = 0;
    const unsigned* M = g_mask + (size_t)img * PRE * NWORDS;
    const int* fin = g_selfin + img * PRE;
    const int b0 = lane * 3;
    const bool v0 = (b0 < NWORDS), v1 = (b0 + 1 < NWORDS), v2 = (b0 + 2 < NWORDS);

    unsigned p0[8], p1[8], p2[8];      // prefetched rows i..i+7
#pragma unroll
    for (int s = 0; s < 8; s++) {
        const unsigned* row = M + (size_t)s * NWORDS + b0;
        p0[s] = v0 ? __ldg(row) : 0u;
        p1[s] = v1 ? __ldg(row + 1) : 0u;
        p2[s] = v2 ? __ldg(row + 2) : 0u;
    }

    for (int ib = 0; ib < PRE; ib += 8) {
#pragma unroll
        for (int s = 0; s < 8; s++) {
            int i = ib + s;
            int wi = i >> 5;
            int owner = wi / 3, sub = wi - owner * 3;
            unsigned myw = (sub == 0) ? r0 : ((sub == 1) ? r1 : r2);
            unsigned word = __shfl_sync(0xffffffffu, myw, owner);
            if (!((word >> (i & 31)) & 1u)) {
                if (lane == 0 && fin[i] && nk < POST) { kept[nk] = i; nk++; }
                r0 |= p0[s]; r1 |= p1[s]; r2 |= p2[s];
            }
            int ip = i + 8;
            if (ip < PRE) {
                const unsigned* row = M + (size_t)ip * NWORDS + b0;
                p0[s] = v0 ? __ldg(row) : 0u;
                p1[s] = v1 ? __ldg(row + 1) : 0u;
                p2[s] = v2 ? __ldg(row + 2) : 0u;
            }
        }
        int cnt = __shfl_sync(0xffffffffu, nk, 0);
        if (cnt >= POST) break;
    }
    if (lane == 0) s_nk = nk;
    __syncwarp();
    int NK = s_nk;

    for (int r = lane; r < POST; r += 32) {
        float4 b = make_float4(0.f, 0.f, 0.f, 0.f);
        float v = 0.f;
        if (r < NK) {
            b = *reinterpret_cast<const float4*>(&g_selbox[((size_t)img * PRE + kept[r]) * 4]);
            v = 1.f;
        }
        float* rp = out + OFF_ROI + ((size_t)img * POST + r) * 4;
        rp[0] = b.x; rp[1] = b.y; rp[2] = b.z; rp[3] = b.w;
        out[OFF_VAL + img * POST + r] = v;
    }
}

// ===================== launch =====================
extern "C" void kernel_launch(void* const* d_in, const int* in_sizes, int n_in,
                              void* d_out, int out_size)
{
    const float* x  = (const float*)d_in[0];
    const float* W1 = (const float*)d_in[1];
    const float* b1 = (const float*)d_in[2];
    const float* Ws = (const float*)d_in[3];
    const float* bs = (const float*)d_in[4];
    const float* Wl = (const float*)d_in[5];
    const float* bl = (const float*)d_in[6];
    const int* imh  = (const int*)d_in[7];
    const int* imw  = (const int*)d_in[8];
    float* out = (float*)d_out;

    cudaFuncSetAttribute(sort_local8k, cudaFuncAttributeMaxDynamicSharedMemorySize, 65536);
    cudaFuncSetAttribute(merge_local8k, cudaFuncAttributeMaxDynamicSharedMemorySize, 65536);
    cudaFuncSetAttribute(conv3x3_kernel, cudaFuncAttributeMaxDynamicSharedMemorySize, CONV_SMEM_B);

    // conv is the 4th launch (the one ncu profiles)
    anchors_kernel<<<(NANCH + 255) / 256, 256>>>(out + OFF_ANC);
    pad_keys_kernel<<<(N_IMG * (NS - NANCH) + 255) / 256, 256>>>();
    wtrans_kernel<<<(KTOT * C_IN + 255) / 256, 256>>>(W1);

    conv3x3_kernel<<<dim3(128, 4), 256, CONV_SMEM_B>>>(x, b1);
    heads_kernel<<<128, 128>>>(Ws, bs, Wl, bl, out);
    boxes_kernel<<<(N_IMG * NANCH + 255) / 256, 256>>>(out + OFF_LOC, imh, imw);

    sort_local8k<<<32, 512, 65536>>>();
    for (int k = 16384; k <= 65536; k <<= 1) {
        for (int j = k >> 1; j >= 8192; j >>= 1)
            sort_global<<<512, 256>>>(k, j);
        merge_local8k<<<32, 512, 65536>>>(k);
    }

    gather_kernel<<<(N_IMG * PRE + 255) / 256, 256>>>();
    iou_kernel<<<(N_IMG * PRE * NWORDS + 255) / 256, 256>>>();
    nms_kernel<<<4, 32>>>(out);
}

// round 17
// speedup vs baseline: 2.2020x; 1.0277x over previous
#include <cuda_runtime.h>
#include <math.h>
#include <stdint.h>

#define N_IMG 4
#define C_IN 512
#define SP 4096              // 64*64 per image
#define KTOT 4608            // 512*9
#define NANCH 36864          // 4096*9
#define NS 65536             // padded sort size per image
#define PRE 3000
#define POST 300
#define NWORDS 94            // ceil(3000/32)

// output layout (concatenated float32, reference return order)
#define OFF_LOC 0
#define OFF_SC  589824
#define OFF_ROI 884736
#define OFF_VAL 889536
#define OFF_ANC 890736

// -------- scratch (static device globals; no allocation) --------
__device__ float g_h[N_IMG * C_IN * SP];          // conv1 output, NCHW
__device__ uint32_t g_wt_hi[KTOT * C_IN];         // W1 transposed hi (tf32 bits), k = r*512+c
__device__ uint32_t g_wt_lo[KTOT * C_IN];         // W1 transposed lo residual (tf32 bits)
__device__ float g_fg[N_IMG * NANCH];             // softmax fg scores
__device__ float g_boxes[N_IMG * NANCH * 4];      // decoded+clipped boxes
__device__ unsigned long long g_keys[N_IMG * NS]; // sort keys
__device__ float g_selbox[N_IMG * PRE * 4];       // top-3000 boxes
__device__ int   g_selfin[N_IMG * PRE];           // finite-score flag
__device__ unsigned g_mask[N_IMG * PRE * NWORDS]; // iou>0.7 bitmask rows

__device__ __forceinline__ float read_scalar(const int* p) {
    int iv = *p;
    if (iv > 0 && iv < (1 << 24)) return (float)iv;
    return *reinterpret_cast<const float*>(p);
}

__device__ __forceinline__ uint32_t f2tf(float f) {
    uint32_t r;
    asm("cvt.rna.tf32.f32 %0, %1;" : "=r"(r) : "f"(f));
    return r;
}

// chained MMA: c += a*b
#define MMA_TF32(c, a, b) \
    asm("mma.sync.aligned.m16n8k8.row.col.f32.tf32.tf32.f32 " \
        "{%0,%1,%2,%3},{%4,%5,%6,%7},{%8,%9},{%0,%1,%2,%3};" \
        : "+f"((c)[0]), "+f"((c)[1]), "+f"((c)[2]), "+f"((c)[3]) \
        : "r"((a)[0]), "r"((a)[1]), "r"((a)[2]), "r"((a)[3]), \
          "r"((b)[0]), "r"((b)[1]))

// fresh MMA: c = a*b + 0   (d != c; kills accumulator bias chains)
#define MMA_TF32_Z(c, a, b) \
    asm("mma.sync.aligned.m16n8k8.row.col.f32.tf32.tf32.f32 " \
        "{%0,%1,%2,%3},{%4,%5,%6,%7},{%8,%9},{%10,%11,%12,%13};" \
        : "=f"((c)[0]), "=f"((c)[1]), "=f"((c)[2]), "=f"((c)[3]) \
        : "r"((a)[0]), "r"((a)[1]), "r"((a)[2]), "r"((a)[3]), \
          "r"((b)[0]), "r"((b)[1]), \
          "f"(0.f), "f"(0.f), "f"(0.f), "f"(0.f))

// ===================== pre-conv kernels (conv must be 4th launch for ncu) =====================
__global__ void anchors_kernel(float* __restrict__ anch_out)
{
    int li = blockIdx.x * blockDim.x + threadIdx.x;
    if (li >= NANCH) return;
    int pix = li / 9;
    int a = li - pix * 9;
    int y = pix >> 6, x = pix & 63;
    int ri = a / 3, si = a - ri * 3;
    float ratio = (ri == 0) ? 0.5f : ((ri == 1) ? 1.0f : 2.0f);
    float scl = (si == 0) ? 8.f : ((si == 1) ? 16.f : 32.f);
    float hs = (16.f * scl) * sqrtf(ratio);
    float ws = (16.f * scl) * sqrtf(1.0f / ratio);
    float sy = (float)(y * 16), sx = (float)(x * 16);
    float* ap = anch_out + (size_t)li * 4;
    ap[0] = sy + (8.f - hs * 0.5f);
    ap[1] = sx + (8.f - ws * 0.5f);
    ap[2] = sy + (8.f + hs * 0.5f);
    ap[3] = sx + (8.f + ws * 0.5f);
}

__global__ void pad_keys_kernel()
{
    int t = blockIdx.x * blockDim.x + threadIdx.x;
    int per = NS - NANCH;
    if (t >= N_IMG * per) return;
    int img = t / per, li = NANCH + (t - img * per);
    g_keys[(size_t)img * NS + li] = 0xFFFFFFFFFFFFFFFFull;
}

// W1[m][c*9+r]  ->  hi/lo tf32 planes at [(r*512+c)*512 + m]
__global__ void wtrans_kernel(const float* __restrict__ W1)
{
    int t = blockIdx.x * blockDim.x + threadIdx.x;
    if (t >= KTOT * C_IN) return;
    int k = t >> 9, m = t & 511;
    int rr = k >> 9, c = k & 511;
    float w = W1[(size_t)m * KTOT + c * 9 + rr];
    uint32_t h = f2tf(w);
    g_wt_hi[t] = h;
    g_wt_lo[t] = f2tf(w - __uint_as_float(h));
}

// ===================== conv 3x3 via mma.sync tf32 (3-pass hi/lo, segmented accum) ==============
#define TPAD 136
#define TILE_F (16 * TPAD)                 // 2176 words per tile
#define BUF_F (4 * TILE_F)                 // Ahi, Alo, Bhi, Blo
#define CONV_SMEM_B (2 * BUF_F * 4)        // 69632 bytes
#define NCH 288

__global__ __launch_bounds__(256, 2) void conv3x3_kernel(
    const float* __restrict__ x, const float* __restrict__ bias)
{
    extern __shared__ uint32_t smu[];
    const int tid = threadIdx.x;
    const int n0 = blockIdx.x * 128;
    const int m0 = blockIdx.y * 128;
    const int wid = tid >> 5, lane = tid & 31;
    const int g = lane >> 2, tk = lane & 3;
    const int wm = wid >> 2, wn = wid & 3;

    // fill coordinates: this thread owns column n, k-rows krow0 + 2*i (i=0..7)
    const int n = tid & 127;
    const int krow0 = tid >> 7;           // 0 or 1
    const int img = n0 >> 12;
    const int col = n0 + n;
    const int ny = (col >> 6) & 63;
    const int nx = col & 63;
    const float* xim = x + (size_t)img * (C_IN * SP);

    float sum[4][4][4];
#pragma unroll
    for (int a = 0; a < 4; a++)
#pragma unroll
        for (int b = 0; b < 4; b++)
#pragma unroll
            for (int c = 0; c < 4; c++) sum[a][b][c] = 0.f;

    uint32_t avh[8], avl[8];
    float bv[8];

#define LOADG(CH) do { \
    const int k0 = (CH) << 4; \
    const int rr = (CH) >> 5; \
    const int cb = k0 & 511; \
    const int ryy = rr / 3; \
    const int dy = ryy - 1, dx = rr - 3 * ryy - 1; \
    const int yy = ny + dy, xx = nx + dx; \
    const bool pred = ((unsigned)yy < 64u) && ((unsigned)xx < 64u); \
    const size_t aoff = ((size_t)(k0 + krow0) << 9) + m0 + n; \
    const uint32_t* aph = g_wt_hi + aoff; \
    const uint32_t* apl = g_wt_lo + aoff; \
    const float* bp = xim + ((size_t)(cb + krow0) << 12) + (yy << 6) + xx; \
    _Pragma("unroll") \
    for (int i = 0; i < 8; i++) { avh[i] = aph[i * 1024]; avl[i] = apl[i * 1024]; } \
    _Pragma("unroll") \
    for (int i = 0; i < 8; i++) bv[i] = pred ? bp[(size_t)i * 8192] : 0.f; \
    } while (0)

#define STORE_AB(BUF) do { \
    uint32_t* SAh = smu + (BUF) * BUF_F + krow0 * TPAD + n; \
    uint32_t* SAl = SAh + TILE_F; \
    uint32_t* SBh = SAh + 2 * TILE_F; \
    uint32_t* SBl = SAh + 3 * TILE_F; \
    _Pragma("unroll") \
    for (int i = 0; i < 8; i++) { \
        SAh[i * 2 * TPAD] = avh[i]; \
        SAl[i * 2 * TPAD] = avl[i]; \
        uint32_t h = f2tf(bv[i]); \
        SBh[i * 2 * TPAD] = h; \
        SBl[i * 2 * TPAD] = f2tf(bv[i] - __uint_as_float(h)); \
    } } while (0)

    LOADG(0);
    STORE_AB(0);
    __syncthreads();

    int buf = 0;
    for (int ch = 0; ch < NCH; ch++) {
        const bool more = ch + 1 < NCH;
        if (more) LOADG(ch + 1);

        {
            const uint32_t* SAh = smu + buf * BUF_F;
            const uint32_t* SAl = SAh + TILE_F;
            const uint32_t* SBh = SAh + 2 * TILE_F;
            const uint32_t* SBl = SAh + 3 * TILE_F;
            const int r0 = tk * TPAD;
            const int r4 = r0 + 4 * TPAD;
#pragma unroll
            for (int ks = 0; ks < 2; ks++) {
                const int ro = ks * 8 * TPAD;
                uint32_t bh[4][2], bl[4][2];
#pragma unroll
                for (int nf = 0; nf < 4; nf++) {
                    const int nb = wn * 32 + nf * 8 + g;
                    bh[nf][0] = SBh[ro + r0 + nb];
                    bh[nf][1] = SBh[ro + r4 + nb];
                    bl[nf][0] = SBl[ro + r0 + nb];
                    bl[nf][1] = SBl[ro + r4 + nb];
                }
#pragma unroll
                for (int mf = 0; mf < 4; mf++) {
                    const int mb = wm * 64 + mf * 16 + g;
                    uint32_t ah[4], al[4];
                    ah[0] = SAh[ro + r0 + mb];   ah[1] = SAh[ro + r0 + mb + 8];
                    ah[2] = SAh[ro + r4 + mb];   ah[3] = SAh[ro + r4 + mb + 8];
                    al[0] = SAl[ro + r0 + mb];   al[1] = SAl[ro + r0 + mb + 8];
                    al[2] = SAl[ro + r4 + mb];   al[3] = SAl[ro + r4 + mb + 8];
#pragma unroll
                    for (int nf = 0; nf < 4; nf++) {
                        float t[4];
                        MMA_TF32_Z(t, ah, bh[nf]);    // partial = Ahi*Bhi
                        MMA_TF32(t, ah, bl[nf]);      // + Ahi*Blo
                        MMA_TF32(t, al, bh[nf]);      // + Alo*Bhi
                        sum[mf][nf][0] += t[0];
                        sum[mf][nf][1] += t[1];
                        sum[mf][nf][2] += t[2];
                        sum[mf][nf][3] += t[3];
                    }
                }
            }
        }

        if (more) STORE_AB(buf ^ 1);
        __syncthreads();
        buf ^= 1;
    }

    // epilogue: bias + relu
    const int spb = n0 & 4095;
#pragma unroll
    for (int mf = 0; mf < 4; mf++) {
        const int m = m0 + wm * 64 + mf * 16 + g;
        const float bv0 = bias[m];
        const float bv1 = bias[m + 8];
        float* h0 = g_h + ((size_t)img * C_IN + m) * SP + spb;
        float* h1 = h0 + 8 * SP;
#pragma unroll
        for (int nf = 0; nf < 4; nf++) {
            const int nn = wn * 32 + nf * 8 + 2 * tk;
            float2 v0, v1;
            v0.x = fmaxf(sum[mf][nf][0] + bv0, 0.f);
            v0.y = fmaxf(sum[mf][nf][1] + bv0, 0.f);
            v1.x = fmaxf(sum[mf][nf][2] + bv1, 0.f);
            v1.y = fmaxf(sum[mf][nf][3] + bv1, 0.f);
            *reinterpret_cast<float2*>(h0 + nn) = v0;
            *reinterpret_cast<float2*>(h1 + nn) = v1;
        }
    }
}

// ===================== heads: 1x1 convs (18 score, 36 loc), transpose, softmax =====================
__global__ __launch_bounds__(128) void heads_kernel(
    const float* __restrict__ Ws, const float* __restrict__ bs,
    const float* __restrict__ Wl, const float* __restrict__ bl,
    float* __restrict__ out)
{
    __shared__ float Wt[54][64];
    const int tid = threadIdx.x;
    const int col = blockIdx.x * 128 + tid;
    const int img = col >> 12;
    const int sp = col & 4095;

    float acc[54];
#pragma unroll
    for (int o = 0; o < 54; o++) acc[o] = 0.f;

    for (int c0 = 0; c0 < C_IN; c0 += 64) {
        for (int i = tid; i < 54 * 64; i += 128) {
            int o = i >> 6, cc = i & 63;
            Wt[o][cc] = (o < 18) ? Ws[o * C_IN + c0 + cc] : Wl[(o - 18) * C_IN + c0 + cc];
        }
        __syncthreads();
        const float* hp = g_h + (size_t)img * C_IN * SP + (size_t)c0 * SP + sp;
#pragma unroll 4
        for (int cc = 0; cc < 64; cc++) {
            float xv = hp[(size_t)cc * SP];
#pragma unroll
            for (int o = 0; o < 54; o++) acc[o] += xv * Wt[o][cc];
        }
        __syncthreads();
    }

    const size_t base9 = (size_t)img * NANCH + (size_t)sp * 9;
#pragma unroll
    for (int o = 0; o < 18; o++) {
        float v = acc[o] + bs[o];
        out[OFF_SC + (base9 + (o >> 1)) * 2 + (o & 1)] = v;
    }
#pragma unroll
    for (int o = 0; o < 36; o++) {
        float v = acc[18 + o] + bl[o];
        out[OFF_LOC + (base9 + (o >> 2)) * 4 + (o & 3)] = v;
    }
#pragma unroll
    for (int a = 0; a < 9; a++) {
        float s0 = acc[2 * a] + bs[2 * a];
        float s1 = acc[2 * a + 1] + bs[2 * a + 1];
        float m = fmaxf(s0, s1);
        float e0 = expf(s0 - m), e1 = expf(s1 - m);
        g_fg[base9 + a] = e1 / (e0 + e1);
    }
}

// ===================== loc2bbox + clip + min-size + sort keys =====================
__global__ void boxes_kernel(const float* __restrict__ locs,
                             const int* __restrict__ imh_p, const int* __restrict__ imw_p)
{
    int t = blockIdx.x * blockDim.x + threadIdx.x;
    if (t >= N_IMG * NANCH) return;
    int img = t / NANCH;
    int li = t - img * NANCH;

    int pix = li / 9;
    int a = li - pix * 9;
    int y = pix >> 6, x = pix & 63;
    int ri = a / 3, si = a - ri * 3;
    float ratio = (ri == 0) ? 0.5f : ((ri == 1) ? 1.0f : 2.0f);
    float scl = (si == 0) ? 8.f : ((si == 1) ? 16.f : 32.f);
    float hs = (16.f * scl) * sqrtf(ratio);
    float ws = (16.f * scl) * sqrtf(1.0f / ratio);
    float sy = (float)(y * 16), sx = (float)(x * 16);
    float ay1 = sy + (8.f - hs * 0.5f);
    float ax1 = sx + (8.f - ws * 0.5f);
    float ay2 = sy + (8.f + hs * 0.5f);
    float ax2 = sx + (8.f + ws * 0.5f);

    const float* lp = locs + ((size_t)img * NANCH + li) * 4;
    float dy = lp[0], dx = lp[1], dh = lp[2], dw = lp[3];
    float ah = ay2 - ay1, aw = ax2 - ax1;
    float acy = ay1 + 0.5f * ah, acx = ax1 + 0.5f * aw;
    float cy = dy * ah + acy, cx = dx * aw + acx;
    float hb = expf(dh) * ah, wb = expf(dw) * aw;

    float imh = read_scalar(imh_p);
    float imw = read_scalar(imw_p);
    float y1 = fminf(fmaxf(cy - 0.5f * hb, 0.f), imh);
    float x1 = fminf(fmaxf(cx - 0.5f * wb, 0.f), imw);
    float y2 = fminf(fmaxf(cy + 0.5f * hb, 0.f), imh);
    float x2 = fminf(fmaxf(cx + 0.5f * wb, 0.f), imw);

    float* bp = g_boxes + ((size_t)img * NANCH + li) * 4;
    bp[0] = y1; bp[1] = x1; bp[2] = y2; bp[3] = x2;

    bool valid = ((y2 - y1) >= 16.f) && ((x2 - x1) >= 16.f);
    float s = valid ? g_fg[(size_t)img * NANCH + li] : -INFINITY;
    unsigned u = __float_as_uint(s);
    unsigned desc = (u & 0x80000000u) ? u : (~u & 0x7FFFFFFFu);   // ascending key = descending score
    g_keys[(size_t)img * NS + li] = ((unsigned long long)desc << 32) | (unsigned)li;
}

// ===================== sort: per-8K ascending bitonic + truncating tournament merge ============
// Each 8192 block sorted ascending; then 3 rounds of pairwise merge keeping the smallest 8192
// (contains the exact top-3000 of the union), finishing with an in-smem bitonic merge.
__global__ __launch_bounds__(512) void sort_local8k()
{
    extern __shared__ unsigned long long s[];
    const int base = blockIdx.x * 8192;
    for (int i = threadIdx.x; i < 8192; i += 512) s[i] = g_keys[base + i];
    __syncthreads();
    for (int k = 2; k <= 8192; k <<= 1) {
        for (int j = k >> 1; j > 0; j >>= 1) {
            for (int t = threadIdx.x; t < 4096; t += 512) {
                int i = ((t & ~(j - 1)) << 1) | (t & (j - 1));
                int l = i | j;
                bool up = ((i & k) == 0);          // ascending in every block
                unsigned long long va = s[i], vb = s[l];
                if ((va > vb) == up) { s[i] = vb; s[l] = va; }
            }
            __syncthreads();
        }
    }
    for (int i = threadIdx.x; i < 8192; i += 512) g_keys[base + i] = s[i];
}

// merge lists A (at img*NS + q*2*gap) and B (= A + gap), both ascending length 8192;
// write the smallest 8192 of the union, ascending, back to A.
__global__ __launch_bounds__(512) void merge_trunc(int gap, int per)
{
    extern __shared__ unsigned long long s[];
    const int img = blockIdx.x / per;
    const int q = blockIdx.x - img * per;
    unsigned long long* A = g_keys + (size_t)img * NS + (size_t)q * 2 * gap;
    const unsigned long long* B = A + gap;

    // stage j=8192 of a 16K bitonic merge: keep mins -> smallest 8192, bitonic sequence
    for (int i = threadIdx.x; i < 8192; i += 512) {
        unsigned long long va = A[i];
        unsigned long long vb = B[8191 - i];
        s[i] = (va < vb) ? va : vb;
    }
    __syncthreads();
    // bitonic merge the 8192 ascending
    for (int j = 4096; j > 0; j >>= 1) {
        for (int t = threadIdx.x; t < 4096; t += 512) {
            int i = ((t & ~(j - 1)) << 1) | (t & (j - 1));
            int l = i | j;
            unsigned long long va = s[i], vb = s[l];
            if (va > vb) { s[i] = vb; s[l] = va; }
        }
        __syncthreads();
    }
    for (int i = threadIdx.x; i < 8192; i += 512) A[i] = s[i];
}

// ===================== gather top-3000 =====================
__global__ void gather_kernel()
{
    int t = blockIdx.x * blockDim.x + threadIdx.x;
    if (t >= N_IMG * PRE) return;
    int img = t / PRE, r = t - img * PRE;
    unsigned long long key = g_keys[(size_t)img * NS + r];
    int li = (int)(key & 0xFFFFFFFFull);
    unsigned desc = (unsigned)(key >> 32);
    g_selfin[img * PRE + r] = (desc < 0xFF800000u) ? 1 : 0;  // finite score
    float4 b = *reinterpret_cast<const float4*>(&g_boxes[((size_t)img * NANCH + li) * 4]);
    *reinterpret_cast<float4*>(&g_selbox[((size_t)img * PRE + r) * 4]) = b;
}

// ===================== IoU > 0.7 bitmask (upper triangle only) =====================
// The greedy scan reads row j's bits only at columns i > j, so words entirely
// below the diagonal are never consulted -> store 0 without computing.
__global__ void iou_kernel()
{
    int t = blockIdx.x * blockDim.x + threadIdx.x;
    if (t >= N_IMG * PRE * NWORDS) return;
    int img = t / (PRE * NWORDS);
    int rem = t - img * (PRE * NWORDS);
    int i = rem / NWORDS;
    int w = rem - i * NWORDS;
    int j0 = w * 32;
    unsigned* dst = &g_mask[((size_t)img * PRE + i) * NWORDS + w];
    if (j0 + 31 < i) { *dst = 0u; return; }     // whole word below diagonal: never read
    const float* B = g_selbox + (size_t)img * PRE * 4;
    float4 bi = *reinterpret_cast<const float4*>(B + (size_t)i * 4);
    float ai = (bi.z - bi.x) * (bi.w - bi.y);
    unsigned bits = 0;
#pragma unroll 4
    for (int jj = 0; jj < 32; jj++) {
        int j = j0 + jj;
        if (j >= PRE) break;
        float4 bj = *reinterpret_cast<const float4*>(B + (size_t)j * 4);
        float yy1 = fmaxf(bi.x, bj.x), xx1 = fmaxf(bi.y, bj.y);
        float yy2 = fminf(bi.z, bj.z), xx2 = fminf(bi.w, bj.w);
        float ih = fmaxf(yy2 - yy1, 0.f), iw = fmaxf(xx2 - xx1, 0.f);
        float inter = ih * iw;
        float aj = (bj.z - bj.x) * (bj.w - bj.y);
        float uni = ai + aj - inter;
        float iou = (uni > 0.f) ? (inter / uni) : 0.f;
        if (iou > 0.7f) bits |= (1u << jj);
    }
    *dst = bits;
}

// ===================== sequential greedy NMS with 8-deep row prefetch =====================
__global__ void nms_kernel(float* __restrict__ out)
{
    const int img = blockIdx.x;
    const int lane = threadIdx.x;
    __shared__ int kept[POST];
    __shared__ int s_nk;
    unsigned r0 = 0, r1 = 0, r2 = 0;   // lane owns removed-words [3*lane .. 3*lane+2]
    int nk = 0;
    const unsigned* M = g_mask + (size_t)img * PRE * NWORDS;
    const int* fin = g_selfin + img * PRE;
    const int b0 = lane * 3;
    const bool v0 = (b0 < NWORDS), v1 = (b0 + 1 < NWORDS), v2 = (b0 + 2 < NWORDS);

    unsigned p0[8], p1[8], p2[8];      // prefetched rows i..i+7
#pragma unroll
    for (int s = 0; s < 8; s++) {
        const unsigned* row = M + (size_t)s * NWORDS + b0;
        p0[s] = v0 ? __ldg(row) : 0u;
        p1[s] = v1 ? __ldg(row + 1) : 0u;
        p2[s] = v2 ? __ldg(row + 2) : 0u;
    }

    for (int ib = 0; ib < PRE; ib += 8) {
#pragma unroll
        for (int s = 0; s < 8; s++) {
            int i = ib + s;
            int wi = i >> 5;
            int owner = wi / 3, sub = wi - owner * 3;
            unsigned myw = (sub == 0) ? r0 : ((sub == 1) ? r1 : r2);
            unsigned word = __shfl_sync(0xffffffffu, myw, owner);
            if (!((word >> (i & 31)) & 1u)) {
                if (lane == 0 && fin[i] && nk < POST) { kept[nk] = i; nk++; }
                r0 |= p0[s]; r1 |= p1[s]; r2 |= p2[s];
            }
            int ip = i + 8;
            if (ip < PRE) {
                const unsigned* row = M + (size_t)ip * NWORDS + b0;
                p0[s] = v0 ? __ldg(row) : 0u;
                p1[s] = v1 ? __ldg(row + 1) : 0u;
                p2[s] = v2 ? __ldg(row + 2) : 0u;
            }
        }
        int cnt = __shfl_sync(0xffffffffu, nk, 0);
        if (cnt >= POST) break;
    }
    if (lane == 0) s_nk = nk;
    __syncwarp();
    int NK = s_nk;

    for (int r = lane; r < POST; r += 32) {
        float4 b = make_float4(0.f, 0.f, 0.f, 0.f);
        float v = 0.f;
        if (r < NK) {
            b = *reinterpret_cast<const float4*>(&g_selbox[((size_t)img * PRE + kept[r]) * 4]);
            v = 1.f;
        }
        float* rp = out + OFF_ROI + ((size_t)img * POST + r) * 4;
        rp[0] = b.x; rp[1] = b.y; rp[2] = b.z; rp[3] = b.w;
        out[OFF_VAL + img * POST + r] = v;
    }
}

// ===================== launch =====================
extern "C" void kernel_launch(void* const* d_in, const int* in_sizes, int n_in,
                              void* d_out, int out_size)
{
    const float* x  = (const float*)d_in[0];
    const float* W1 = (const float*)d_in[1];
    const float* b1 = (const float*)d_in[2];
    const float* Ws = (const float*)d_in[3];
    const float* bs = (const float*)d_in[4];
    const float* Wl = (const float*)d_in[5];
    const float* bl = (const float*)d_in[6];
    const int* imh  = (const int*)d_in[7];
    const int* imw  = (const int*)d_in[8];
    float* out = (float*)d_out;

    cudaFuncSetAttribute(sort_local8k, cudaFuncAttributeMaxDynamicSharedMemorySize, 65536);
    cudaFuncSetAttribute(merge_trunc, cudaFuncAttributeMaxDynamicSharedMemorySize, 65536);
    cudaFuncSetAttribute(conv3x3_kernel, cudaFuncAttributeMaxDynamicSharedMemorySize, CONV_SMEM_B);

    // conv is the 4th launch (the one ncu profiles)
    anchors_kernel<<<(NANCH + 255) / 256, 256>>>(out + OFF_ANC);
    pad_keys_kernel<<<(N_IMG * (NS - NANCH) + 255) / 256, 256>>>();
    wtrans_kernel<<<(KTOT * C_IN + 255) / 256, 256>>>(W1);

    conv3x3_kernel<<<dim3(128, 4), 256, CONV_SMEM_B>>>(x, b1);
    heads_kernel<<<128, 128>>>(Ws, bs, Wl, bl, out);
    boxes_kernel<<<(N_IMG * NANCH + 255) / 256, 256>>>(out + OFF_LOC, imh, imw);

    sort_local8k<<<32, 512, 65536>>>();
    merge_trunc<<<16, 512, 65536>>>(8192, 4);
    merge_trunc<<<8, 512, 65536>>>(16384, 2);
    merge_trunc<<<4, 512, 65536>>>(32768, 1);

    gather_kernel<<<(N_IMG * PRE + 255) / 256, 256>>>();
    iou_kernel<<<(N_IMG * PRE * NWORDS + 255) / 256, 256>>>();
    nms_kernel<<<4, 32>>>(out);
}